// round 2
// baseline (speedup 1.0000x reference)
#include <cuda_runtime.h>
#include <math.h>

#define BATCH 2
#define SEQ   2048
#define NH    16
#define HD    64
#define HID   1024            // NH*HD
#define MROWS (BATCH*SEQ)     // 4096

// Scratch (no allocations allowed): q, k, v in [B, S, NH*HD] layout + RoPE tables
__device__ float g_q[MROWS * HID];
__device__ float g_k[MROWS * HID];
__device__ float g_v[MROWS * HID];
__device__ float g_cos[SEQ * 32];
__device__ float g_sin[SEQ * 32];

// ---------------------------------------------------------------------------
// Fused QKV projection: Y = X @ W^T ; X[M,K] row-major, W[N,K] row-major.
// blockIdx.z selects (Wq->g_q, Wk->g_k, Wv->g_v).
// BM=BN=128, BK=16, 256 threads, 8x8 register tile per thread.
// ---------------------------------------------------------------------------
__global__ __launch_bounds__(256, 2)
void qkv_gemm(const float* __restrict__ X,
              const float* __restrict__ Wq,
              const float* __restrict__ Wk,
              const float* __restrict__ Wv) {
    const int K = HID, N = HID;
    __shared__ float As[16][132];   // transposed: As[k][m], padded
    __shared__ float Bs[16][132];   // transposed: Bs[k][n], padded

    const float* W = (blockIdx.z == 0) ? Wq : (blockIdx.z == 1) ? Wk : Wv;
    float* Y       = (blockIdx.z == 0) ? g_q : (blockIdx.z == 1) ? g_k : g_v;

    const int m0 = blockIdx.y * 128;
    const int n0 = blockIdx.x * 128;
    const int t  = threadIdx.x;
    const int lr = t >> 2;           // 0..63
    const int lc = (t & 3) * 4;      // 0,4,8,12
    const int ty = t >> 4;           // 0..15
    const int tx = t & 15;           // 0..15

    float acc[8][8];
#pragma unroll
    for (int i = 0; i < 8; i++)
#pragma unroll
        for (int j = 0; j < 8; j++) acc[i][j] = 0.0f;

    for (int k0 = 0; k0 < K; k0 += 16) {
#pragma unroll
        for (int rep = 0; rep < 2; rep++) {
            int row = rep * 64 + lr;
            float4 xa = *(const float4*)&X[(size_t)(m0 + row) * K + k0 + lc];
            As[lc + 0][row] = xa.x; As[lc + 1][row] = xa.y;
            As[lc + 2][row] = xa.z; As[lc + 3][row] = xa.w;
            float4 wb = *(const float4*)&W[(size_t)(n0 + row) * K + k0 + lc];
            Bs[lc + 0][row] = wb.x; Bs[lc + 1][row] = wb.y;
            Bs[lc + 2][row] = wb.z; Bs[lc + 3][row] = wb.w;
        }
        __syncthreads();
#pragma unroll
        for (int kk = 0; kk < 16; kk++) {
            float4 a0 = *(const float4*)&As[kk][ty * 8];
            float4 a1 = *(const float4*)&As[kk][ty * 8 + 4];
            float4 b0 = *(const float4*)&Bs[kk][tx * 8];
            float4 b1 = *(const float4*)&Bs[kk][tx * 8 + 4];
            float a[8] = {a0.x, a0.y, a0.z, a0.w, a1.x, a1.y, a1.z, a1.w};
            float b[8] = {b0.x, b0.y, b0.z, b0.w, b1.x, b1.y, b1.z, b1.w};
#pragma unroll
            for (int i = 0; i < 8; i++)
#pragma unroll
                for (int j = 0; j < 8; j++) acc[i][j] = fmaf(a[i], b[j], acc[i][j]);
        }
        __syncthreads();
    }

#pragma unroll
    for (int i = 0; i < 8; i++) {
        size_t base = (size_t)(m0 + ty * 8 + i) * N + n0 + tx * 8;
        float4 o0 = make_float4(acc[i][0], acc[i][1], acc[i][2], acc[i][3]);
        float4 o1 = make_float4(acc[i][4], acc[i][5], acc[i][6], acc[i][7]);
        *(float4*)&Y[base]     = o0;
        *(float4*)&Y[base + 4] = o1;
    }
}

// ---------------------------------------------------------------------------
// RoPE tables: angle math in double so fp32 cos/sin match the fp32 reference.
// ---------------------------------------------------------------------------
__global__ void rope_table() {
    int idx = blockIdx.x * blockDim.x + threadIdx.x;   // SEQ*32 = 65536
    if (idx >= SEQ * 32) return;
    int s = idx >> 5;
    int j = idx & 31;
    double inv = pow(10000.0, -(double)j / 32.0);
    double a = (double)s * inv;
    g_cos[idx] = (float)cos(a);
    g_sin[idx] = (float)sin(a);
}

// In-place RoPE on q and k. One thread per (row, head, pair).
__global__ void rope_apply() {
    int idx = blockIdx.x * blockDim.x + threadIdx.x;   // MROWS*NH*32
    if (idx >= MROWS * NH * 32) return;
    int j    = idx & 31;
    int head = (idx >> 5) & (NH - 1);
    int m    = idx >> 9;
    int s    = m & (SEQ - 1);
    float c  = g_cos[s * 32 + j];
    float sn = g_sin[s * 32 + j];
    int base = m * HID + head * HD + j;
    float qlo = g_q[base], qhi = g_q[base + 32];
    g_q[base]      = fmaf(qlo, c, -qhi * sn);
    g_q[base + 32] = fmaf(qhi, c,  qlo * sn);
    float klo = g_k[base], khi = g_k[base + 32];
    g_k[base]      = fmaf(klo, c, -khi * sn);
    g_k[base + 32] = fmaf(khi, c,  klo * sn);
}

// ---------------------------------------------------------------------------
// Flash attention fp32. Grid: (S/64, NH, B). 256 threads.
// Thread (ty,tx) in 16x16 grid owns queries ty*4..+3 and (keys|dims) tx*4..+3.
// SMEM rows padded to 65 floats (2-way conflicts worst case).
// ---------------------------------------------------------------------------
#define AR 65
#define ATTN_SMEM (4 * 64 * AR * 4)

__global__ __launch_bounds__(256, 2)
void attn_kernel(float* __restrict__ out) {
    extern __shared__ float sh[];
    float* Qs = sh;
    float* Ks = sh + 64 * AR;
    float* Vs = sh + 2 * 64 * AR;
    float* Ps = sh + 3 * 64 * AR;

    const int t  = threadIdx.x;
    const int ty = t >> 4, tx = t & 15;
    const int b  = blockIdx.z, h = blockIdx.y;
    const int q0 = blockIdx.x * 64;

    const float* qptr = g_q + (size_t)b * SEQ * HID + h * HD;
    const float* kptr = g_k + (size_t)b * SEQ * HID + h * HD;
    const float* vptr = g_v + (size_t)b * SEQ * HID + h * HD;

    const int lr = t >> 2;          // 0..63 (row within tile)
    const int lc = (t & 3) * 16;    // 0,16,32,48

    // Load Q tile, prescaled by 1/sqrt(64)
#pragma unroll
    for (int u = 0; u < 16; u += 4) {
        float4 v = *(const float4*)&qptr[(size_t)(q0 + lr) * HID + lc + u];
        Qs[lr * AR + lc + u + 0] = v.x * 0.125f;
        Qs[lr * AR + lc + u + 1] = v.y * 0.125f;
        Qs[lr * AR + lc + u + 2] = v.z * 0.125f;
        Qs[lr * AR + lc + u + 3] = v.w * 0.125f;
    }

    float m_i[4], l_i[4], acc[4][4];
#pragma unroll
    for (int i = 0; i < 4; i++) {
        m_i[i] = -1e30f; l_i[i] = 0.0f;
#pragma unroll
        for (int j = 0; j < 4; j++) acc[i][j] = 0.0f;
    }

    for (int k0 = 0; k0 < SEQ; k0 += 64) {
        __syncthreads();   // previous PV done before overwriting Ks/Vs
#pragma unroll
        for (int u = 0; u < 16; u += 4) {
            float4 kv = *(const float4*)&kptr[(size_t)(k0 + lr) * HID + lc + u];
            Ks[lr * AR + lc + u + 0] = kv.x; Ks[lr * AR + lc + u + 1] = kv.y;
            Ks[lr * AR + lc + u + 2] = kv.z; Ks[lr * AR + lc + u + 3] = kv.w;
            float4 vv = *(const float4*)&vptr[(size_t)(k0 + lr) * HID + lc + u];
            Vs[lr * AR + lc + u + 0] = vv.x; Vs[lr * AR + lc + u + 1] = vv.y;
            Vs[lr * AR + lc + u + 2] = vv.z; Vs[lr * AR + lc + u + 3] = vv.w;
        }
        __syncthreads();

        // Scores: sc[i][j] = sum_d Qs[q][d] * Ks[k][d]
        float sc[4][4];
#pragma unroll
        for (int i = 0; i < 4; i++)
#pragma unroll
            for (int j = 0; j < 4; j++) sc[i][j] = 0.0f;
#pragma unroll 16
        for (int d = 0; d < 64; d++) {
            float qv[4], kv[4];
#pragma unroll
            for (int i = 0; i < 4; i++) qv[i] = Qs[(ty * 4 + i) * AR + d];
#pragma unroll
            for (int j = 0; j < 4; j++) kv[j] = Ks[(tx * 4 + j) * AR + d];
#pragma unroll
            for (int i = 0; i < 4; i++)
#pragma unroll
                for (int j = 0; j < 4; j++) sc[i][j] = fmaf(qv[i], kv[j], sc[i][j]);
        }

        // Online softmax (row stats replicated across the 16 tx lanes of each ty)
#pragma unroll
        for (int i = 0; i < 4; i++) {
            float mx = fmaxf(fmaxf(sc[i][0], sc[i][1]), fmaxf(sc[i][2], sc[i][3]));
#pragma unroll
            for (int off = 8; off >= 1; off >>= 1)
                mx = fmaxf(mx, __shfl_xor_sync(0xffffffffu, mx, off));
            float mnew = fmaxf(m_i[i], mx);
            float corr = __expf(m_i[i] - mnew);
            float rs = 0.0f;
#pragma unroll
            for (int j = 0; j < 4; j++) {
                sc[i][j] = __expf(sc[i][j] - mnew);
                rs += sc[i][j];
            }
#pragma unroll
            for (int off = 8; off >= 1; off >>= 1)
                rs += __shfl_xor_sync(0xffffffffu, rs, off);
            l_i[i] = l_i[i] * corr + rs;
            m_i[i] = mnew;
#pragma unroll
            for (int j = 0; j < 4; j++) acc[i][j] *= corr;
#pragma unroll
            for (int j = 0; j < 4; j++)
                Ps[(ty * 4 + i) * AR + tx * 4 + j] = sc[i][j];
        }
        __syncthreads();   // Ps visible to all

        // PV: acc[i][j] += sum_k Ps[q][k] * Vs[k][d]
#pragma unroll 16
        for (int kk = 0; kk < 64; kk++) {
            float pv[4], vv[4];
#pragma unroll
            for (int i = 0; i < 4; i++) pv[i] = Ps[(ty * 4 + i) * AR + kk];
#pragma unroll
            for (int j = 0; j < 4; j++) vv[j] = Vs[kk * AR + tx * 4 + j];
#pragma unroll
            for (int i = 0; i < 4; i++)
#pragma unroll
                for (int j = 0; j < 4; j++) acc[i][j] = fmaf(pv[i], vv[j], acc[i][j]);
        }
    }

    // Normalize and write: out[b, s, h*64 + d]
#pragma unroll
    for (int i = 0; i < 4; i++) {
        float inv_l = 1.0f / l_i[i];
        size_t base = (size_t)(b * SEQ + q0 + ty * 4 + i) * HID + h * HD + tx * 4;
        float4 o = make_float4(acc[i][0] * inv_l, acc[i][1] * inv_l,
                               acc[i][2] * inv_l, acc[i][3] * inv_l);
        *(float4*)&out[base] = o;
    }
}

// ---------------------------------------------------------------------------
extern "C" void kernel_launch(void* const* d_in, const int* in_sizes, int n_in,
                              void* d_out, int out_size) {
    const float* X  = (const float*)d_in[0];
    const float* Wq = (const float*)d_in[1];
    const float* Wk = (const float*)d_in[2];
    const float* Wv = (const float*)d_in[3];
    float* out = (float*)d_out;

    qkv_gemm<<<dim3(HID / 128, MROWS / 128, 3), 256>>>(X, Wq, Wk, Wv);
    rope_table<<<(SEQ * 32 + 255) / 256, 256>>>();
    rope_apply<<<(MROWS * NH * 32 + 255) / 256, 256>>>();
    cudaFuncSetAttribute(attn_kernel, cudaFuncAttributeMaxDynamicSharedMemorySize, ATTN_SMEM);
    attn_kernel<<<dim3(SEQ / 64, NH, BATCH), 256, ATTN_SMEM>>>(out);
}

// round 3
// speedup vs baseline: 2.8103x; 2.8103x over previous
#include <cuda_runtime.h>
#include <math.h>
#include <stdint.h>

#define BATCH 2
#define SEQ   2048
#define NH    16
#define HD    64
#define HID   1024            // NH*HD
#define MROWS (BATCH*SEQ)     // 4096

// Scratch (no allocations allowed)
__device__ float g_q[MROWS * HID];
__device__ float g_k[MROWS * HID];
__device__ float g_v[MROWS * HID];
__device__ float g_cos[SEQ * 32];
__device__ float g_sin[SEQ * 32];

__device__ __forceinline__ uint32_t f2tf32(float x) {
    uint32_t u;
    asm("cvt.rna.tf32.f32 %0, %1;" : "=r"(u) : "f"(x));
    return u;
}

__device__ __forceinline__ void mma_tf32(float c[4], const uint32_t a[4], const uint32_t b[2]) {
    asm volatile(
        "mma.sync.aligned.m16n8k8.row.col.f32.tf32.tf32.f32 "
        "{%0,%1,%2,%3},{%4,%5,%6,%7},{%8,%9},{%0,%1,%2,%3};"
        : "+f"(c[0]), "+f"(c[1]), "+f"(c[2]), "+f"(c[3])
        : "r"(a[0]), "r"(a[1]), "r"(a[2]), "r"(a[3]), "r"(b[0]), "r"(b[1]));
}

// ---------------------------------------------------------------------------
// QKV projection with TF32 tensor cores: Y = X @ W^T.
// X[M,K] row-major, W[N,K] row-major. blockIdx.z selects q/k/v.
// Block tile 128x128, K-step 32. 8 warps in 4x2 (warp tile 32x64).
// ---------------------------------------------------------------------------
#define APAD 36
__global__ __launch_bounds__(256)
void qkv_gemm(const float* __restrict__ X,
              const float* __restrict__ Wq,
              const float* __restrict__ Wk,
              const float* __restrict__ Wv) {
    __shared__ uint32_t As[128 * APAD];
    __shared__ uint32_t Bs[128 * APAD];

    const float* W = (blockIdx.z == 0) ? Wq : (blockIdx.z == 1) ? Wk : Wv;
    float* Y       = (blockIdx.z == 0) ? g_q : (blockIdx.z == 1) ? g_k : g_v;

    const int m0 = blockIdx.y * 128;
    const int n0 = blockIdx.x * 128;
    const int tid  = threadIdx.x;
    const int warp = tid >> 5;
    const int lane = tid & 31;
    const int g = lane >> 2;          // 0..7
    const int t = lane & 3;           // 0..3
    const int wm0 = (warp >> 1) * 32; // 0,32,64,96
    const int wn0 = (warp & 1) * 64;  // 0,64

    float acc[2][8][4];
#pragma unroll
    for (int mt = 0; mt < 2; mt++)
#pragma unroll
        for (int nt = 0; nt < 8; nt++)
#pragma unroll
            for (int e = 0; e < 4; e++) acc[mt][nt][e] = 0.0f;

    for (int k0 = 0; k0 < HID; k0 += 32) {
#pragma unroll
        for (int u = 0; u < 4; u++) {
            int idx = tid + u * 256;
            int row = idx >> 3;
            int c4  = (idx & 7) * 4;
            float4 xa = *(const float4*)&X[(size_t)(m0 + row) * HID + k0 + c4];
            As[row * APAD + c4 + 0] = f2tf32(xa.x);
            As[row * APAD + c4 + 1] = f2tf32(xa.y);
            As[row * APAD + c4 + 2] = f2tf32(xa.z);
            As[row * APAD + c4 + 3] = f2tf32(xa.w);
            float4 wb = *(const float4*)&W[(size_t)(n0 + row) * HID + k0 + c4];
            Bs[row * APAD + c4 + 0] = f2tf32(wb.x);
            Bs[row * APAD + c4 + 1] = f2tf32(wb.y);
            Bs[row * APAD + c4 + 2] = f2tf32(wb.z);
            Bs[row * APAD + c4 + 3] = f2tf32(wb.w);
        }
        __syncthreads();

#pragma unroll
        for (int kc = 0; kc < 4; kc++) {
            uint32_t a[2][4];
#pragma unroll
            for (int mt = 0; mt < 2; mt++) {
                int r = wm0 + mt * 16;
                a[mt][0] = As[(r + g)     * APAD + kc * 8 + t];
                a[mt][1] = As[(r + g + 8) * APAD + kc * 8 + t];
                a[mt][2] = As[(r + g)     * APAD + kc * 8 + t + 4];
                a[mt][3] = As[(r + g + 8) * APAD + kc * 8 + t + 4];
            }
#pragma unroll
            for (int nt = 0; nt < 8; nt++) {
                uint32_t b[2];
                int col = wn0 + nt * 8 + g;
                b[0] = Bs[col * APAD + kc * 8 + t];
                b[1] = Bs[col * APAD + kc * 8 + t + 4];
#pragma unroll
                for (int mt = 0; mt < 2; mt++) mma_tf32(acc[mt][nt], a[mt], b);
            }
        }
        __syncthreads();
    }

#pragma unroll
    for (int mt = 0; mt < 2; mt++)
#pragma unroll
        for (int nt = 0; nt < 8; nt++) {
            int row0 = m0 + wm0 + mt * 16 + g;
            int col  = n0 + wn0 + nt * 8 + 2 * t;
            *(float2*)&Y[(size_t)row0 * HID + col] =
                make_float2(acc[mt][nt][0], acc[mt][nt][1]);
            *(float2*)&Y[(size_t)(row0 + 8) * HID + col] =
                make_float2(acc[mt][nt][2], acc[mt][nt][3]);
        }
}

// ---------------------------------------------------------------------------
// RoPE tables + in-place apply (unchanged — negligible cost)
// ---------------------------------------------------------------------------
__global__ void rope_table() {
    int idx = blockIdx.x * blockDim.x + threadIdx.x;
    if (idx >= SEQ * 32) return;
    int s = idx >> 5;
    int j = idx & 31;
    double inv = pow(10000.0, -(double)j / 32.0);
    double a = (double)s * inv;
    g_cos[idx] = (float)cos(a);
    g_sin[idx] = (float)sin(a);
}

__global__ void rope_apply() {
    int idx = blockIdx.x * blockDim.x + threadIdx.x;
    if (idx >= MROWS * NH * 32) return;
    int j    = idx & 31;
    int head = (idx >> 5) & (NH - 1);
    int m    = idx >> 9;
    int s    = m & (SEQ - 1);
    float c  = g_cos[s * 32 + j];
    float sn = g_sin[s * 32 + j];
    int base = m * HID + head * HD + j;
    float qlo = g_q[base], qhi = g_q[base + 32];
    g_q[base]      = fmaf(qlo, c, -qhi * sn);
    g_q[base + 32] = fmaf(qhi, c,  qlo * sn);
    float klo = g_k[base], khi = g_k[base + 32];
    g_k[base]      = fmaf(klo, c, -khi * sn);
    g_k[base + 32] = fmaf(khi, c,  klo * sn);
}

// ---------------------------------------------------------------------------
// Flash attention with TF32 tensor cores.
// Block: 128 queries x 1 head. 8 warps, 16 query rows per warp.
// Key tiles of 64. QK^T and PV via m16n8k8 TF32; softmax fp32 in regs.
// ---------------------------------------------------------------------------
#define KPAD 68
#define KS_OFF 0
#define VS_OFF (64 * KPAD)
#define PS_OFF (2 * 64 * KPAD)
#define ATTN_SMEM ((2 * 64 * KPAD + 8 * 16 * KPAD) * 4)

__global__ __launch_bounds__(256)
void attn_kernel(float* __restrict__ out) {
    extern __shared__ uint32_t sh[];
    uint32_t* Ks = sh + KS_OFF;
    uint32_t* Vs = sh + VS_OFF;

    const int tid  = threadIdx.x;
    const int warp = tid >> 5;
    const int lane = tid & 31;
    const int g = lane >> 2;
    const int t = lane & 3;
    const int h = blockIdx.y & (NH - 1);
    const int b = blockIdx.y >> 4;
    const int q0 = blockIdx.x * 128;

    uint32_t* Pw = sh + PS_OFF + warp * 16 * KPAD;

    const float* qptr = g_q + (size_t)b * SEQ * HID + h * HD;
    const float* kptr = g_k + (size_t)b * SEQ * HID + h * HD;
    const float* vptr = g_v + (size_t)b * SEQ * HID + h * HD;

    // Stage this warp's 16 Q rows (prescaled by 1/8) into its P region, grab frags
#pragma unroll
    for (int i = lane; i < 256; i += 32) {
        int row = i >> 4;
        int c4  = (i & 15) * 4;
        float4 v = *(const float4*)&qptr[(size_t)(q0 + warp * 16 + row) * HID + c4];
        Pw[row * KPAD + c4 + 0] = f2tf32(v.x * 0.125f);
        Pw[row * KPAD + c4 + 1] = f2tf32(v.y * 0.125f);
        Pw[row * KPAD + c4 + 2] = f2tf32(v.z * 0.125f);
        Pw[row * KPAD + c4 + 3] = f2tf32(v.w * 0.125f);
    }
    __syncwarp();
    uint32_t qa[8][4];
#pragma unroll
    for (int kc = 0; kc < 8; kc++) {
        qa[kc][0] = Pw[g       * KPAD + kc * 8 + t];
        qa[kc][1] = Pw[(g + 8) * KPAD + kc * 8 + t];
        qa[kc][2] = Pw[g       * KPAD + kc * 8 + t + 4];
        qa[kc][3] = Pw[(g + 8) * KPAD + kc * 8 + t + 4];
    }
    __syncwarp();

    float m_i[2] = {-1e30f, -1e30f};
    float l_i[2] = {0.0f, 0.0f};
    float o[8][4];
#pragma unroll
    for (int nt = 0; nt < 8; nt++)
#pragma unroll
        for (int e = 0; e < 4; e++) o[nt][e] = 0.0f;

    for (int k0 = 0; k0 < SEQ; k0 += 64) {
        __syncthreads();   // previous PV done before overwriting Ks/Vs
#pragma unroll
        for (int u = 0; u < 4; u++) {
            int idx = tid + u * 256;
            int row = idx >> 4;
            int c4  = (idx & 15) * 4;
            float4 kv = *(const float4*)&kptr[(size_t)(k0 + row) * HID + c4];
            Ks[row * KPAD + c4 + 0] = f2tf32(kv.x);
            Ks[row * KPAD + c4 + 1] = f2tf32(kv.y);
            Ks[row * KPAD + c4 + 2] = f2tf32(kv.z);
            Ks[row * KPAD + c4 + 3] = f2tf32(kv.w);
            float4 vv = *(const float4*)&vptr[(size_t)(k0 + row) * HID + c4];
            Vs[row * KPAD + c4 + 0] = f2tf32(vv.x);
            Vs[row * KPAD + c4 + 1] = f2tf32(vv.y);
            Vs[row * KPAD + c4 + 2] = f2tf32(vv.z);
            Vs[row * KPAD + c4 + 3] = f2tf32(vv.w);
        }
        __syncthreads();

        // S = Qs @ Ks^T : per warp 16x64
        float s[8][4];
#pragma unroll
        for (int nt = 0; nt < 8; nt++)
#pragma unroll
            for (int e = 0; e < 4; e++) s[nt][e] = 0.0f;
#pragma unroll
        for (int nt = 0; nt < 8; nt++) {
#pragma unroll
            for (int kc = 0; kc < 8; kc++) {
                uint32_t bfrag[2];
                bfrag[0] = Ks[(nt * 8 + g) * KPAD + kc * 8 + t];
                bfrag[1] = Ks[(nt * 8 + g) * KPAD + kc * 8 + t + 4];
                mma_tf32(s[nt], qa[kc], bfrag);
            }
        }

        // Online softmax per row (row g -> elems [0],[1]; row g+8 -> [2],[3])
#pragma unroll
        for (int half = 0; half < 2; half++) {
            int e0 = half * 2;
            float mx = -1e30f;
#pragma unroll
            for (int nt = 0; nt < 8; nt++)
                mx = fmaxf(mx, fmaxf(s[nt][e0], s[nt][e0 + 1]));
            mx = fmaxf(mx, __shfl_xor_sync(0xffffffffu, mx, 1));
            mx = fmaxf(mx, __shfl_xor_sync(0xffffffffu, mx, 2));
            float mnew = fmaxf(m_i[half], mx);
            float corr = __expf(m_i[half] - mnew);
            float rs = 0.0f;
#pragma unroll
            for (int nt = 0; nt < 8; nt++) {
                float p0 = __expf(s[nt][e0]     - mnew);
                float p1 = __expf(s[nt][e0 + 1] - mnew);
                rs += p0 + p1;
                Pw[(g + half * 8) * KPAD + nt * 8 + 2 * t]     = f2tf32(p0);
                Pw[(g + half * 8) * KPAD + nt * 8 + 2 * t + 1] = f2tf32(p1);
            }
            rs += __shfl_xor_sync(0xffffffffu, rs, 1);
            rs += __shfl_xor_sync(0xffffffffu, rs, 2);
            l_i[half] = l_i[half] * corr + rs;
            m_i[half] = mnew;
#pragma unroll
            for (int nt = 0; nt < 8; nt++) {
                o[nt][e0]     *= corr;
                o[nt][e0 + 1] *= corr;
            }
        }
        __syncwarp();

        // ctx += P @ V : 16x64 @ 64x64
#pragma unroll
        for (int kc = 0; kc < 8; kc++) {
            uint32_t pa[4];
            pa[0] = Pw[g       * KPAD + kc * 8 + t];
            pa[1] = Pw[(g + 8) * KPAD + kc * 8 + t];
            pa[2] = Pw[g       * KPAD + kc * 8 + t + 4];
            pa[3] = Pw[(g + 8) * KPAD + kc * 8 + t + 4];
#pragma unroll
            for (int nt = 0; nt < 8; nt++) {
                uint32_t bfrag[2];
                bfrag[0] = Vs[(kc * 8 + t)     * KPAD + nt * 8 + g];
                bfrag[1] = Vs[(kc * 8 + t + 4) * KPAD + nt * 8 + g];
                mma_tf32(o[nt], pa, bfrag);
            }
        }
        __syncwarp();   // P reads done before next iteration's stores
    }

    // Normalize and write out[b, s, h*64 + d]
#pragma unroll
    for (int half = 0; half < 2; half++) {
        float inv_l = 1.0f / l_i[half];
        int row = q0 + warp * 16 + g + half * 8;
#pragma unroll
        for (int nt = 0; nt < 8; nt++) {
            size_t base = (size_t)(b * SEQ + row) * HID + h * HD + nt * 8 + 2 * t;
            *(float2*)&out[base] = make_float2(o[nt][half * 2] * inv_l,
                                               o[nt][half * 2 + 1] * inv_l);
        }
    }
}

// ---------------------------------------------------------------------------
extern "C" void kernel_launch(void* const* d_in, const int* in_sizes, int n_in,
                              void* d_out, int out_size) {
    const float* X  = (const float*)d_in[0];
    const float* Wq = (const float*)d_in[1];
    const float* Wk = (const float*)d_in[2];
    const float* Wv = (const float*)d_in[3];
    float* out = (float*)d_out;

    qkv_gemm<<<dim3(HID / 128, MROWS / 128, 3), 256>>>(X, Wq, Wk, Wv);
    rope_table<<<(SEQ * 32 + 255) / 256, 256>>>();
    rope_apply<<<(MROWS * NH * 32 + 255) / 256, 256>>>();
    cudaFuncSetAttribute(attn_kernel, cudaFuncAttributeMaxDynamicSharedMemorySize, ATTN_SMEM);
    attn_kernel<<<dim3(SEQ / 128, NH * BATCH), 256, ATTN_SMEM>>>(out);
}

// round 4
// speedup vs baseline: 3.0258x; 1.0767x over previous
#include <cuda_runtime.h>
#include <math.h>
#include <stdint.h>

#define BATCH 2
#define SEQ   2048
#define NH    16
#define HD    64
#define HID   1024            // NH*HD
#define MROWS (BATCH*SEQ)     // 4096

// Scratch (no allocations allowed)
__device__ float g_q[MROWS * HID];
__device__ float g_k[MROWS * HID];
__device__ float g_v[MROWS * HID];
__device__ float g_cos[SEQ * 32];
__device__ float g_sin[SEQ * 32];

__device__ __forceinline__ uint32_t f2tf32(float x) {
    uint32_t u;
    asm("cvt.rna.tf32.f32 %0, %1;" : "=r"(u) : "f"(x));
    return u;
}

__device__ __forceinline__ void mma_tf32(float c[4], const uint32_t a[4], const uint32_t b[2]) {
    asm volatile(
        "mma.sync.aligned.m16n8k8.row.col.f32.tf32.tf32.f32 "
        "{%0,%1,%2,%3},{%4,%5,%6,%7},{%8,%9},{%0,%1,%2,%3};"
        : "+f"(c[0]), "+f"(c[1]), "+f"(c[2]), "+f"(c[3])
        : "r"(a[0]), "r"(a[1]), "r"(a[2]), "r"(a[3]), "r"(b[0]), "r"(b[1]));
}

// Word-address XOR swizzle key (flips word bits 3,4 -> 32B/64B granules).
#define XORK(x) ((((x) & 1) << 4) | (((x) & 2) << 2))

// ---------------------------------------------------------------------------
// QKV projection (unchanged from round 2 — known good).
// ---------------------------------------------------------------------------
#define APAD 36
__global__ __launch_bounds__(256)
void qkv_gemm(const float* __restrict__ X,
              const float* __restrict__ Wq,
              const float* __restrict__ Wk,
              const float* __restrict__ Wv) {
    __shared__ uint32_t As[128 * APAD];
    __shared__ uint32_t Bs[128 * APAD];

    const float* W = (blockIdx.z == 0) ? Wq : (blockIdx.z == 1) ? Wk : Wv;
    float* Y       = (blockIdx.z == 0) ? g_q : (blockIdx.z == 1) ? g_k : g_v;

    const int m0 = blockIdx.y * 128;
    const int n0 = blockIdx.x * 128;
    const int tid  = threadIdx.x;
    const int warp = tid >> 5;
    const int lane = tid & 31;
    const int g = lane >> 2;
    const int t = lane & 3;
    const int wm0 = (warp >> 1) * 32;
    const int wn0 = (warp & 1) * 64;

    float acc[2][8][4];
#pragma unroll
    for (int mt = 0; mt < 2; mt++)
#pragma unroll
        for (int nt = 0; nt < 8; nt++)
#pragma unroll
            for (int e = 0; e < 4; e++) acc[mt][nt][e] = 0.0f;

    for (int k0 = 0; k0 < HID; k0 += 32) {
#pragma unroll
        for (int u = 0; u < 4; u++) {
            int idx = tid + u * 256;
            int row = idx >> 3;
            int c4  = (idx & 7) * 4;
            float4 xa = *(const float4*)&X[(size_t)(m0 + row) * HID + k0 + c4];
            As[row * APAD + c4 + 0] = f2tf32(xa.x);
            As[row * APAD + c4 + 1] = f2tf32(xa.y);
            As[row * APAD + c4 + 2] = f2tf32(xa.z);
            As[row * APAD + c4 + 3] = f2tf32(xa.w);
            float4 wb = *(const float4*)&W[(size_t)(n0 + row) * HID + k0 + c4];
            Bs[row * APAD + c4 + 0] = f2tf32(wb.x);
            Bs[row * APAD + c4 + 1] = f2tf32(wb.y);
            Bs[row * APAD + c4 + 2] = f2tf32(wb.z);
            Bs[row * APAD + c4 + 3] = f2tf32(wb.w);
        }
        __syncthreads();

#pragma unroll
        for (int kc = 0; kc < 4; kc++) {
            uint32_t a[2][4];
#pragma unroll
            for (int mt = 0; mt < 2; mt++) {
                int r = wm0 + mt * 16;
                a[mt][0] = As[(r + g)     * APAD + kc * 8 + t];
                a[mt][1] = As[(r + g + 8) * APAD + kc * 8 + t];
                a[mt][2] = As[(r + g)     * APAD + kc * 8 + t + 4];
                a[mt][3] = As[(r + g + 8) * APAD + kc * 8 + t + 4];
            }
#pragma unroll
            for (int nt = 0; nt < 8; nt++) {
                uint32_t b[2];
                int col = wn0 + nt * 8 + g;
                b[0] = Bs[col * APAD + kc * 8 + t];
                b[1] = Bs[col * APAD + kc * 8 + t + 4];
#pragma unroll
                for (int mt = 0; mt < 2; mt++) mma_tf32(acc[mt][nt], a[mt], b);
            }
        }
        __syncthreads();
    }

#pragma unroll
    for (int mt = 0; mt < 2; mt++)
#pragma unroll
        for (int nt = 0; nt < 8; nt++) {
            int row0 = m0 + wm0 + mt * 16 + g;
            int col  = n0 + wn0 + nt * 8 + 2 * t;
            *(float2*)&Y[(size_t)row0 * HID + col] =
                make_float2(acc[mt][nt][0], acc[mt][nt][1]);
            *(float2*)&Y[(size_t)(row0 + 8) * HID + col] =
                make_float2(acc[mt][nt][2], acc[mt][nt][3]);
        }
}

// ---------------------------------------------------------------------------
// RoPE (unchanged)
// ---------------------------------------------------------------------------
__global__ void rope_table() {
    int idx = blockIdx.x * blockDim.x + threadIdx.x;
    if (idx >= SEQ * 32) return;
    int s = idx >> 5;
    int j = idx & 31;
    double inv = pow(10000.0, -(double)j / 32.0);
    double a = (double)s * inv;
    g_cos[idx] = (float)cos(a);
    g_sin[idx] = (float)sin(a);
}

__global__ void rope_apply() {
    int idx = blockIdx.x * blockDim.x + threadIdx.x;
    if (idx >= MROWS * NH * 32) return;
    int j    = idx & 31;
    int head = (idx >> 5) & (NH - 1);
    int m    = idx >> 9;
    int s    = m & (SEQ - 1);
    float c  = g_cos[s * 32 + j];
    float sn = g_sin[s * 32 + j];
    int base = m * HID + head * HD + j;
    float qlo = g_q[base], qhi = g_q[base + 32];
    g_q[base]      = fmaf(qlo, c, -qhi * sn);
    g_q[base + 32] = fmaf(qhi, c,  qlo * sn);
    float klo = g_k[base], khi = g_k[base + 32];
    g_k[base]      = fmaf(klo, c, -khi * sn);
    g_k[base + 32] = fmaf(khi, c,  klo * sn);
}

// ---------------------------------------------------------------------------
// Flash attention, fragment-major SMEM, 32 query rows per warp.
// Block: 128 threads (4 warps), 128 queries. Key tiles of 64.
// SMEM (words): Kf[4096] | Vf[4096] | Qf[4 warps][2048] | Pf[4 warps][2048]
// Fragment layouts (all addresses in 32-bit words):
//   B-frag (K):  (kc*8+nb)*64 + ((lane8*2) ^ XORK(kc)) + e      e: k-col t / t+4
//   B-frag (V):  (kc*8+nb)*64 + ((lane8*2) ^ XORK(nb)) + e
//   A-frag (Q):  (mt*8+kc)*128 + ((lane8*4) ^ ((kc&3)<<2)) + e  e: (hi) + 2*(mhalf)
//   A-frag (P):  mt*1024 + kc*128 + tw*32 + g*4 + (hi + 2*h)
// ---------------------------------------------------------------------------
#define ATTN_SMEM (24576 * 4)   // 96 KB

__global__ __launch_bounds__(128)
void attn_kernel(float* __restrict__ out) {
    extern __shared__ uint32_t sh[];
    const int tid  = threadIdx.x;
    const int warp = tid >> 5;
    const int lane = tid & 31;
    const int g = lane >> 2;
    const int t = lane & 3;
    const int h = blockIdx.y & (NH - 1);
    const int b = blockIdx.y >> 4;
    const int q0 = blockIdx.x * 128;

    uint32_t* Kf = sh;
    uint32_t* Vf = sh + 4096;
    uint32_t* Qf = sh + 8192  + warp * 2048;
    uint32_t* Pf = sh + 16384 + warp * 2048;

    const float* qptr = g_q + (size_t)b * SEQ * HID + h * HD;
    const float* kptr = g_k + (size_t)b * SEQ * HID + h * HD;
    const float* vptr = g_v + (size_t)b * SEQ * HID + h * HD;

    // ---- Stage this warp's 32 Q rows fragment-major (prescaled by 1/8) ----
#pragma unroll
    for (int i = lane; i < 512; i += 32) {
        int r  = i >> 4;            // 0..31 local row
        int c4 = (i & 15) * 4;      // 0..60
        float4 v = *(const float4*)&qptr[(size_t)(q0 + warp * 32 + r) * HID + c4];
        int mt = r >> 4, kc = c4 >> 3;
        int e  = ((c4 >> 2) & 1) + 2 * ((r >> 3) & 1);
        int base = (mt * 8 + kc) * 128;
        int lb = (r & 7) * 4;
        uint32_t xk = (uint32_t)((kc & 3) << 2);
        Qf[base + (((lb + 0) * 4) ^ xk) + e] = f2tf32(v.x * 0.125f);
        Qf[base + (((lb + 1) * 4) ^ xk) + e] = f2tf32(v.y * 0.125f);
        Qf[base + (((lb + 2) * 4) ^ xk) + e] = f2tf32(v.z * 0.125f);
        Qf[base + (((lb + 3) * 4) ^ xk) + e] = f2tf32(v.w * 0.125f);
    }

    float m_i[2][2], l_i[2][2];
    float o[2][8][4];
#pragma unroll
    for (int mt = 0; mt < 2; mt++) {
        m_i[mt][0] = m_i[mt][1] = -1e30f;
        l_i[mt][0] = l_i[mt][1] = 0.0f;
#pragma unroll
        for (int nb = 0; nb < 8; nb++)
#pragma unroll
            for (int e = 0; e < 4; e++) o[mt][nb][e] = 0.0f;
    }

    for (int k0 = 0; k0 < SEQ; k0 += 64) {
        __syncthreads();   // prior tile's fragment reads complete

        // ---- Stage K and V tiles fragment-major ----
#pragma unroll
        for (int u = 0; u < 8; u++) {
            int idx = tid + u * 128;       // 0..1023
            int r   = idx >> 4;            // key row 0..63
            int c4  = (idx & 15) * 4;      // dim 0..60
            float4 kv = *(const float4*)&kptr[(size_t)(k0 + r) * HID + c4];
            {
                int kc = c4 >> 3, nb = r >> 3, e = (c4 >> 2) & 1;
                int fb = (kc * 8 + nb) * 64;
                int lb = (r & 7) * 4;
                uint32_t xk = XORK(kc);
                Kf[fb + (((lb + 0) * 2) ^ xk) + e] = f2tf32(kv.x);
                Kf[fb + (((lb + 1) * 2) ^ xk) + e] = f2tf32(kv.y);
                Kf[fb + (((lb + 2) * 2) ^ xk) + e] = f2tf32(kv.z);
                Kf[fb + (((lb + 3) * 2) ^ xk) + e] = f2tf32(kv.w);
            }
            float4 vv = *(const float4*)&vptr[(size_t)(k0 + r) * HID + c4];
            {
                int kc = r >> 3, nb = c4 >> 3, tv = r & 3, e = (r >> 2) & 1;
                int fb = (kc * 8 + nb) * 64;
                int cb = c4 & 7;
                uint32_t xk = XORK(nb);
                Vf[fb + ((((cb + 0) * 4 + tv) * 2) ^ xk) + e] = f2tf32(vv.x);
                Vf[fb + ((((cb + 1) * 4 + tv) * 2) ^ xk) + e] = f2tf32(vv.y);
                Vf[fb + ((((cb + 2) * 4 + tv) * 2) ^ xk) + e] = f2tf32(vv.z);
                Vf[fb + ((((cb + 3) * 4 + tv) * 2) ^ xk) + e] = f2tf32(vv.w);
            }
        }
        __syncthreads();

        // ---- S = Q @ K^T : 32x64 per warp ----
        float s[2][8][4];
#pragma unroll
        for (int mt = 0; mt < 2; mt++)
#pragma unroll
            for (int nb = 0; nb < 8; nb++)
#pragma unroll
                for (int e = 0; e < 4; e++) s[mt][nb][e] = 0.0f;

#pragma unroll
        for (int kc = 0; kc < 8; kc++) {
            uint32_t a[2][4];
#pragma unroll
            for (int mt = 0; mt < 2; mt++) {
                uint4 w = *(const uint4*)&Qf[(mt * 8 + kc) * 128 +
                                             (((g * 4 + t) * 4) ^ ((kc & 3) << 2))];
                a[mt][0] = w.x; a[mt][1] = w.z; a[mt][2] = w.y; a[mt][3] = w.w;
            }
#pragma unroll
            for (int nb = 0; nb < 8; nb++) {
                uint2 bv = *(const uint2*)&Kf[(kc * 8 + nb) * 64 +
                                              (((g * 4 + t) * 2) ^ XORK(kc))];
                uint32_t bb[2] = {bv.x, bv.y};
                mma_tf32(s[0][nb], a[0], bb);
                mma_tf32(s[1][nb], a[1], bb);
            }
        }

        // ---- Online softmax + write P fragments ----
#pragma unroll
        for (int mt = 0; mt < 2; mt++) {
#pragma unroll
            for (int hh = 0; hh < 2; hh++) {
                const int e0 = hh * 2;
                float mx = -1e30f;
#pragma unroll
                for (int nb = 0; nb < 8; nb++)
                    mx = fmaxf(mx, fmaxf(s[mt][nb][e0], s[mt][nb][e0 + 1]));
                mx = fmaxf(mx, __shfl_xor_sync(0xffffffffu, mx, 1));
                mx = fmaxf(mx, __shfl_xor_sync(0xffffffffu, mx, 2));
                float mnew = fmaxf(m_i[mt][hh], mx);
                float corr = __expf(m_i[mt][hh] - mnew);
                float rs = 0.0f;
                int pw0 = mt * 1024 + ((2 * t) & 3)     * 32 + g * 4 + (t >> 1) + 2 * hh;
                int pw1 = mt * 1024 + ((2 * t + 1) & 3) * 32 + g * 4 + (t >> 1) + 2 * hh;
#pragma unroll
                for (int nb = 0; nb < 8; nb++) {
                    float p0 = __expf(s[mt][nb][e0]     - mnew);
                    float p1 = __expf(s[mt][nb][e0 + 1] - mnew);
                    rs += p0 + p1;
                    Pf[pw0 + nb * 128] = f2tf32(p0);
                    Pf[pw1 + nb * 128] = f2tf32(p1);
                }
                rs += __shfl_xor_sync(0xffffffffu, rs, 1);
                rs += __shfl_xor_sync(0xffffffffu, rs, 2);
                l_i[mt][hh] = l_i[mt][hh] * corr + rs;
                m_i[mt][hh] = mnew;
#pragma unroll
                for (int nb = 0; nb < 8; nb++) {
                    o[mt][nb][e0]     *= corr;
                    o[mt][nb][e0 + 1] *= corr;
                }
            }
        }
        __syncwarp();

        // ---- ctx += P @ V : 32x64 per warp ----
#pragma unroll
        for (int kc = 0; kc < 8; kc++) {
            uint32_t pa[2][4];
#pragma unroll
            for (int mt = 0; mt < 2; mt++) {
                uint4 w = *(const uint4*)&Pf[mt * 1024 + kc * 128 + t * 32 + g * 4];
                pa[mt][0] = w.x; pa[mt][1] = w.z; pa[mt][2] = w.y; pa[mt][3] = w.w;
            }
#pragma unroll
            for (int nb = 0; nb < 8; nb++) {
                uint2 bv = *(const uint2*)&Vf[(kc * 8 + nb) * 64 +
                                              (((g * 4 + t) * 2) ^ XORK(nb))];
                uint32_t bb[2] = {bv.x, bv.y};
                mma_tf32(o[0][nb], pa[0], bb);
                mma_tf32(o[1][nb], pa[1], bb);
            }
        }
    }

    // ---- Normalize and write out[b, s, h*64 + d] ----
#pragma unroll
    for (int mt = 0; mt < 2; mt++)
#pragma unroll
        for (int hh = 0; hh < 2; hh++) {
            float inv_l = 1.0f / l_i[mt][hh];
            int row = q0 + warp * 32 + mt * 16 + g + 8 * hh;
#pragma unroll
            for (int nb = 0; nb < 8; nb++) {
                size_t base = (size_t)(b * SEQ + row) * HID + h * HD + nb * 8 + 2 * t;
                *(float2*)&out[base] = make_float2(o[mt][nb][2 * hh]     * inv_l,
                                                   o[mt][nb][2 * hh + 1] * inv_l);
            }
        }
}

// ---------------------------------------------------------------------------
extern "C" void kernel_launch(void* const* d_in, const int* in_sizes, int n_in,
                              void* d_out, int out_size) {
    const float* X  = (const float*)d_in[0];
    const float* Wq = (const float*)d_in[1];
    const float* Wk = (const float*)d_in[2];
    const float* Wv = (const float*)d_in[3];
    float* out = (float*)d_out;

    qkv_gemm<<<dim3(HID / 128, MROWS / 128, 3), 256>>>(X, Wq, Wk, Wv);
    rope_table<<<(SEQ * 32 + 255) / 256, 256>>>();
    rope_apply<<<(MROWS * NH * 32 + 255) / 256, 256>>>();
    cudaFuncSetAttribute(attn_kernel, cudaFuncAttributeMaxDynamicSharedMemorySize, ATTN_SMEM);
    attn_kernel<<<dim3(SEQ / 128, NH * BATCH), 128, ATTN_SMEM>>>(out);
}

// round 6
// speedup vs baseline: 4.3747x; 1.4458x over previous
#include <cuda_runtime.h>
#include <cuda_fp16.h>
#include <math.h>
#include <stdint.h>

#define BATCH 2
#define SEQ   2048
#define NH    16
#define HD    64
#define HID   1024            // NH*HD
#define MROWS (BATCH*SEQ)     // 4096

// Scratch (no allocations allowed)
__device__ float g_q[MROWS * HID];
__device__ float g_k[MROWS * HID];
__device__ float g_v[MROWS * HID];
__device__ float g_cos[SEQ * 32];
__device__ float g_sin[SEQ * 32];

__device__ __forceinline__ uint32_t f2tf32(float x) {
    uint32_t u;
    asm("cvt.rna.tf32.f32 %0, %1;" : "=r"(u) : "f"(x));
    return u;
}

__device__ __forceinline__ void mma_tf32(float c[4], const uint32_t a[4], const uint32_t b[2]) {
    asm volatile(
        "mma.sync.aligned.m16n8k8.row.col.f32.tf32.tf32.f32 "
        "{%0,%1,%2,%3},{%4,%5,%6,%7},{%8,%9},{%0,%1,%2,%3};"
        : "+f"(c[0]), "+f"(c[1]), "+f"(c[2]), "+f"(c[3])
        : "r"(a[0]), "r"(a[1]), "r"(a[2]), "r"(a[3]), "r"(b[0]), "r"(b[1]));
}

__device__ __forceinline__ void mma_f16(float c[4], const uint32_t a[4],
                                        uint32_t b0, uint32_t b1) {
    asm volatile(
        "mma.sync.aligned.m16n8k16.row.col.f32.f16.f16.f32 "
        "{%0,%1,%2,%3},{%4,%5,%6,%7},{%8,%9},{%0,%1,%2,%3};"
        : "+f"(c[0]), "+f"(c[1]), "+f"(c[2]), "+f"(c[3])
        : "r"(a[0]), "r"(a[1]), "r"(a[2]), "r"(a[3]), "r"(b0), "r"(b1));
}

__device__ __forceinline__ uint32_t packh2(float lo, float hi) {
    __half2 h = __floats2half2_rn(lo, hi);
    return *(uint32_t*)&h;
}

// Bank-spread swizzle key for [row][pair] half2 layouts (32 words/row).
__device__ __forceinline__ int FSW(int d) { return ((d & 7) << 2) | ((d >> 3) & 3); }

// ---------------------------------------------------------------------------
// QKV projection (unchanged — known good, next round's target).
// ---------------------------------------------------------------------------
#define APAD 36
__global__ __launch_bounds__(256)
void qkv_gemm(const float* __restrict__ X,
              const float* __restrict__ Wq,
              const float* __restrict__ Wk,
              const float* __restrict__ Wv) {
    __shared__ uint32_t As[128 * APAD];
    __shared__ uint32_t Bs[128 * APAD];

    const float* W = (blockIdx.z == 0) ? Wq : (blockIdx.z == 1) ? Wk : Wv;
    float* Y       = (blockIdx.z == 0) ? g_q : (blockIdx.z == 1) ? g_k : g_v;

    const int m0 = blockIdx.y * 128;
    const int n0 = blockIdx.x * 128;
    const int tid  = threadIdx.x;
    const int warp = tid >> 5;
    const int lane = tid & 31;
    const int g = lane >> 2;
    const int t = lane & 3;
    const int wm0 = (warp >> 1) * 32;
    const int wn0 = (warp & 1) * 64;

    float acc[2][8][4];
#pragma unroll
    for (int mt = 0; mt < 2; mt++)
#pragma unroll
        for (int nt = 0; nt < 8; nt++)
#pragma unroll
            for (int e = 0; e < 4; e++) acc[mt][nt][e] = 0.0f;

    for (int k0 = 0; k0 < HID; k0 += 32) {
#pragma unroll
        for (int u = 0; u < 4; u++) {
            int idx = tid + u * 256;
            int row = idx >> 3;
            int c4  = (idx & 7) * 4;
            float4 xa = *(const float4*)&X[(size_t)(m0 + row) * HID + k0 + c4];
            As[row * APAD + c4 + 0] = f2tf32(xa.x);
            As[row * APAD + c4 + 1] = f2tf32(xa.y);
            As[row * APAD + c4 + 2] = f2tf32(xa.z);
            As[row * APAD + c4 + 3] = f2tf32(xa.w);
            float4 wb = *(const float4*)&W[(size_t)(n0 + row) * HID + k0 + c4];
            Bs[row * APAD + c4 + 0] = f2tf32(wb.x);
            Bs[row * APAD + c4 + 1] = f2tf32(wb.y);
            Bs[row * APAD + c4 + 2] = f2tf32(wb.z);
            Bs[row * APAD + c4 + 3] = f2tf32(wb.w);
        }
        __syncthreads();

#pragma unroll
        for (int kc = 0; kc < 4; kc++) {
            uint32_t a[2][4];
#pragma unroll
            for (int mt = 0; mt < 2; mt++) {
                int r = wm0 + mt * 16;
                a[mt][0] = As[(r + g)     * APAD + kc * 8 + t];
                a[mt][1] = As[(r + g + 8) * APAD + kc * 8 + t];
                a[mt][2] = As[(r + g)     * APAD + kc * 8 + t + 4];
                a[mt][3] = As[(r + g + 8) * APAD + kc * 8 + t + 4];
            }
#pragma unroll
            for (int nt = 0; nt < 8; nt++) {
                uint32_t b[2];
                int col = wn0 + nt * 8 + g;
                b[0] = Bs[col * APAD + kc * 8 + t];
                b[1] = Bs[col * APAD + kc * 8 + t + 4];
#pragma unroll
                for (int mt = 0; mt < 2; mt++) mma_tf32(acc[mt][nt], a[mt], b);
            }
        }
        __syncthreads();
    }

#pragma unroll
    for (int mt = 0; mt < 2; mt++)
#pragma unroll
        for (int nt = 0; nt < 8; nt++) {
            int row0 = m0 + wm0 + mt * 16 + g;
            int col  = n0 + wn0 + nt * 8 + 2 * t;
            *(float2*)&Y[(size_t)row0 * HID + col] =
                make_float2(acc[mt][nt][0], acc[mt][nt][1]);
            *(float2*)&Y[(size_t)(row0 + 8) * HID + col] =
                make_float2(acc[mt][nt][2], acc[mt][nt][3]);
        }
}

// ---------------------------------------------------------------------------
// RoPE tables (rope_apply is now fused into attention staging)
// ---------------------------------------------------------------------------
__global__ void rope_table() {
    int idx = blockIdx.x * blockDim.x + threadIdx.x;
    if (idx >= SEQ * 32) return;
    int s = idx >> 5;
    int j = idx & 31;
    double inv = pow(10000.0, -(double)j / 32.0);
    double a = (double)s * inv;
    g_cos[idx] = (float)cos(a);
    g_sin[idx] = (float)sin(a);
}

// ---------------------------------------------------------------------------
// Flash attention, fp16 m16n8k16. 128 threads (4 warps), 128 queries/CTA,
// 32 query rows per warp, 64-key tiles. Q frags + P live in registers.
// SMEM layouts (uint32 words, 32 half2 words per row):
//   Kh[key][pair]: word = key*32 + ((dim>>1)   ^ FSW(key))   (RoPE applied)
//   Vh[dim][pair]: word = dim*32 + ((key>>1)   ^ FSW(dim))
//   Qs[row][pair]: word = row*32 + ((dim>>1)   ^ FSW(row))   (staging only)
// ---------------------------------------------------------------------------
__global__ __launch_bounds__(128)
void attn_kernel(float* __restrict__ out) {
    __shared__ uint32_t sh[4096];     // 16 KB
    uint32_t* Kh = sh;                // 2048 words
    uint32_t* Vh = sh + 2048;         // 2048 words

    const int tid  = threadIdx.x;
    const int warp = tid >> 5;
    const int lane = tid & 31;
    const int g = lane >> 2;
    const int t = lane & 3;
    const int h = blockIdx.y & (NH - 1);
    const int b = blockIdx.y >> 4;
    const int q0 = blockIdx.x * 128;

    const float* qptr = g_q + (size_t)b * SEQ * HID + h * HD;
    const float* kptr = g_k + (size_t)b * SEQ * HID + h * HD;
    const float* vptr = g_v + (size_t)b * SEQ * HID + h * HD;

    // ---- Stage Q (RoPE + 1/8 scale) into this warp's scratch, grab frags ----
    uint32_t* Qs = sh + warp * 1024;  // 32 rows x 32 words
#pragma unroll
    for (int it = 0; it < 8; it++) {
        int idx2 = lane + it * 32;
        int dg = idx2 & 7;           // dim group: dims dg*4..+3 and +32
        int r  = idx2 >> 3;          // 0..31
        int row = q0 + warp * 32 + r;
        const float* qr = qptr + (size_t)row * HID;
        float4 lo = *(const float4*)&qr[dg * 4];
        float4 hi = *(const float4*)&qr[dg * 4 + 32];
        float4 cz = *(const float4*)&g_cos[row * 32 + dg * 4];
        float4 sz = *(const float4*)&g_sin[row * 32 + dg * 4];
        float a0 = (lo.x * cz.x - hi.x * sz.x) * 0.125f;
        float a1 = (lo.y * cz.y - hi.y * sz.y) * 0.125f;
        float a2 = (lo.z * cz.z - hi.z * sz.z) * 0.125f;
        float a3 = (lo.w * cz.w - hi.w * sz.w) * 0.125f;
        float b0 = (hi.x * cz.x + lo.x * sz.x) * 0.125f;
        float b1 = (hi.y * cz.y + lo.y * sz.y) * 0.125f;
        float b2 = (hi.z * cz.z + lo.z * sz.z) * 0.125f;
        float b3 = (hi.w * cz.w + lo.w * sz.w) * 0.125f;
        int fr = FSW(r);
        Qs[r * 32 + ((dg * 2 + 0)  ^ fr)] = packh2(a0, a1);
        Qs[r * 32 + ((dg * 2 + 1)  ^ fr)] = packh2(a2, a3);
        Qs[r * 32 + ((dg * 2 + 16) ^ fr)] = packh2(b0, b1);
        Qs[r * 32 + ((dg * 2 + 17) ^ fr)] = packh2(b2, b3);
    }
    __syncwarp();
    uint32_t qa[2][4][4];
#pragma unroll
    for (int mt = 0; mt < 2; mt++) {
        int ra = mt * 16 + g, rb = mt * 16 + 8 + g;
        int fa = FSW(ra), fb = FSW(rb);
#pragma unroll
        for (int kb = 0; kb < 4; kb++) {
            qa[mt][kb][0] = Qs[ra * 32 + ((kb * 8 + t)     ^ fa)];
            qa[mt][kb][1] = Qs[rb * 32 + ((kb * 8 + t)     ^ fb)];
            qa[mt][kb][2] = Qs[ra * 32 + ((kb * 8 + t + 4) ^ fa)];
            qa[mt][kb][3] = Qs[rb * 32 + ((kb * 8 + t + 4) ^ fb)];
        }
    }

    float m_i[2][2], l_i[2][2];
    float o[2][8][4];
#pragma unroll
    for (int mt = 0; mt < 2; mt++) {
        m_i[mt][0] = m_i[mt][1] = -1e30f;
        l_i[mt][0] = l_i[mt][1] = 0.0f;
#pragma unroll
        for (int nb = 0; nb < 8; nb++)
#pragma unroll
            for (int e = 0; e < 4; e++) o[mt][nb][e] = 0.0f;
    }

    for (int k0 = 0; k0 < SEQ; k0 += 64) {
        __syncthreads();   // Q frag reads / previous tile reads complete

        // ---- Stage K (with RoPE) ----
#pragma unroll
        for (int u = 0; u < 4; u++) {
            int idx = tid + u * 128;
            int dg = idx & 7;
            int r  = idx >> 3;        // 0..63
            int pos = k0 + r;
            const float* kr = kptr + (size_t)pos * HID;
            float4 lo = *(const float4*)&kr[dg * 4];
            float4 hi = *(const float4*)&kr[dg * 4 + 32];
            float4 cz = *(const float4*)&g_cos[pos * 32 + dg * 4];
            float4 sz = *(const float4*)&g_sin[pos * 32 + dg * 4];
            int fr = FSW(r);
            Kh[r * 32 + ((dg * 2 + 0)  ^ fr)] =
                packh2(lo.x * cz.x - hi.x * sz.x, lo.y * cz.y - hi.y * sz.y);
            Kh[r * 32 + ((dg * 2 + 1)  ^ fr)] =
                packh2(lo.z * cz.z - hi.z * sz.z, lo.w * cz.w - hi.w * sz.w);
            Kh[r * 32 + ((dg * 2 + 16) ^ fr)] =
                packh2(hi.x * cz.x + lo.x * sz.x, hi.y * cz.y + lo.y * sz.y);
            Kh[r * 32 + ((dg * 2 + 17) ^ fr)] =
                packh2(hi.z * cz.z + lo.z * sz.z, hi.w * cz.w + lo.w * sz.w);
        }
        // ---- Stage V (transposed: [dim][keypair]) ----
#pragma unroll
        for (int u = 0; u < 4; u++) {
            int idx = tid + u * 128;
            int c4 = (idx & 15) * 4;  // dim group
            int kp = idx >> 4;        // key pair 0..31
            const float* v0 = vptr + (size_t)(k0 + 2 * kp) * HID;
            float4 va = *(const float4*)&v0[c4];
            float4 vb = *(const float4*)&v0[HID + c4];
            Vh[(c4 + 0) * 32 + (kp ^ FSW(c4 + 0))] = packh2(va.x, vb.x);
            Vh[(c4 + 1) * 32 + (kp ^ FSW(c4 + 1))] = packh2(va.y, vb.y);
            Vh[(c4 + 2) * 32 + (kp ^ FSW(c4 + 2))] = packh2(va.z, vb.z);
            Vh[(c4 + 3) * 32 + (kp ^ FSW(c4 + 3))] = packh2(va.w, vb.w);
        }
        __syncthreads();

        // ---- S = Q @ K^T : 32x64 per warp ----
        float s[2][8][4];
#pragma unroll
        for (int mt = 0; mt < 2; mt++)
#pragma unroll
            for (int nb = 0; nb < 8; nb++)
#pragma unroll
                for (int e = 0; e < 4; e++) s[mt][nb][e] = 0.0f;

#pragma unroll
        for (int kb = 0; kb < 4; kb++) {
#pragma unroll
            for (int nb = 0; nb < 8; nb++) {
                int key = nb * 8 + g;
                int fk = FSW(key);
                uint32_t b0 = Kh[key * 32 + ((kb * 8 + t)     ^ fk)];
                uint32_t b1 = Kh[key * 32 + ((kb * 8 + t + 4) ^ fk)];
                mma_f16(s[0][nb], qa[0][kb], b0, b1);
                mma_f16(s[1][nb], qa[1][kb], b0, b1);
            }
        }

        // ---- Online softmax; pack P into fp16 A-frags (registers only) ----
        uint32_t pa[2][4][4];
#pragma unroll
        for (int mt = 0; mt < 2; mt++) {
#pragma unroll
            for (int hh = 0; hh < 2; hh++) {
                const int e0 = hh * 2;
                float mx = -1e30f;
#pragma unroll
                for (int nb = 0; nb < 8; nb++)
                    mx = fmaxf(mx, fmaxf(s[mt][nb][e0], s[mt][nb][e0 + 1]));
                mx = fmaxf(mx, __shfl_xor_sync(0xffffffffu, mx, 1));
                mx = fmaxf(mx, __shfl_xor_sync(0xffffffffu, mx, 2));
                float mnew = fmaxf(m_i[mt][hh], mx);
                float corr = __expf(m_i[mt][hh] - mnew);
                float rs = 0.0f;
#pragma unroll
                for (int nb = 0; nb < 8; nb++) {
                    float p0 = __expf(s[mt][nb][e0]     - mnew);
                    float p1 = __expf(s[mt][nb][e0 + 1] - mnew);
                    rs += p0 + p1;
                    s[mt][nb][e0]     = p0;
                    s[mt][nb][e0 + 1] = p1;
                }
                rs += __shfl_xor_sync(0xffffffffu, rs, 1);
                rs += __shfl_xor_sync(0xffffffffu, rs, 2);
                l_i[mt][hh] = l_i[mt][hh] * corr + rs;
                m_i[mt][hh] = mnew;
#pragma unroll
                for (int nb = 0; nb < 8; nb++) {
                    o[mt][nb][e0]     *= corr;
                    o[mt][nb][e0 + 1] *= corr;
                }
            }
            // c-layout: [0]=(g,2t) [1]=(g,2t+1) [2]=(g+8,2t) [3]=(g+8,2t+1)
            // A-frag kb: a0=(g,16kb+2t,+1) a1=(g+8,..) a2=(g,16kb+8+2t,+1) a3=(g+8,..)
#pragma unroll
            for (int kb = 0; kb < 4; kb++) {
                pa[mt][kb][0] = packh2(s[mt][2 * kb][0],     s[mt][2 * kb][1]);
                pa[mt][kb][1] = packh2(s[mt][2 * kb][2],     s[mt][2 * kb][3]);
                pa[mt][kb][2] = packh2(s[mt][2 * kb + 1][0], s[mt][2 * kb + 1][1]);
                pa[mt][kb][3] = packh2(s[mt][2 * kb + 1][2], s[mt][2 * kb + 1][3]);
            }
        }

        // ---- ctx += P @ V : 32x64 per warp ----
#pragma unroll
        for (int kb = 0; kb < 4; kb++) {
#pragma unroll
            for (int nb = 0; nb < 8; nb++) {
                int dim = nb * 8 + g;
                int fd = FSW(dim);
                uint32_t b0 = Vh[dim * 32 + ((kb * 8 + t)     ^ fd)];
                uint32_t b1 = Vh[dim * 32 + ((kb * 8 + t + 4) ^ fd)];
                mma_f16(o[0][nb], pa[0][kb], b0, b1);
                mma_f16(o[1][nb], pa[1][kb], b0, b1);
            }
        }
    }

    // ---- Normalize and write out[b, s, h*64 + d] ----
#pragma unroll
    for (int mt = 0; mt < 2; mt++)
#pragma unroll
        for (int hh = 0; hh < 2; hh++) {
            float inv_l = 1.0f / l_i[mt][hh];
            int row = q0 + warp * 32 + mt * 16 + g + 8 * hh;
#pragma unroll
            for (int nb = 0; nb < 8; nb++) {
                size_t base = (size_t)(b * SEQ + row) * HID + h * HD + nb * 8 + 2 * t;
                *(float2*)&out[base] = make_float2(o[mt][nb][2 * hh]     * inv_l,
                                                   o[mt][nb][2 * hh + 1] * inv_l);
            }
        }
}

// ---------------------------------------------------------------------------
extern "C" void kernel_launch(void* const* d_in, const int* in_sizes, int n_in,
                              void* d_out, int out_size) {
    const float* X  = (const float*)d_in[0];
    const float* Wq = (const float*)d_in[1];
    const float* Wk = (const float*)d_in[2];
    const float* Wv = (const float*)d_in[3];
    float* out = (float*)d_out;

    qkv_gemm<<<dim3(HID / 128, MROWS / 128, 3), 256>>>(X, Wq, Wk, Wv);
    rope_table<<<(SEQ * 32 + 255) / 256, 256>>>();
    attn_kernel<<<dim3(SEQ / 128, NH * BATCH), 128>>>(out);
}

// round 7
// speedup vs baseline: 4.3828x; 1.0018x over previous
#include <cuda_runtime.h>
#include <cuda_fp16.h>
#include <math.h>
#include <stdint.h>

#define BATCH 2
#define SEQ   2048
#define NH    16
#define HD    64
#define HID   1024            // NH*HD
#define MROWS (BATCH*SEQ)     // 4096

// Scratch (no allocations allowed)
__device__ float g_q[MROWS * HID];
__device__ float g_k[MROWS * HID];
__device__ float g_v[MROWS * HID];
__device__ float g_cos[SEQ * 32];
__device__ float g_sin[SEQ * 32];

__device__ __forceinline__ uint32_t f2tf32(float x) {
    uint32_t u;
    asm("cvt.rna.tf32.f32 %0, %1;" : "=r"(u) : "f"(x));
    return u;
}

__device__ __forceinline__ void mma_tf32(float c[4], const uint32_t a[4], const uint32_t b[2]) {
    asm volatile(
        "mma.sync.aligned.m16n8k8.row.col.f32.tf32.tf32.f32 "
        "{%0,%1,%2,%3},{%4,%5,%6,%7},{%8,%9},{%0,%1,%2,%3};"
        : "+f"(c[0]), "+f"(c[1]), "+f"(c[2]), "+f"(c[3])
        : "r"(a[0]), "r"(a[1]), "r"(a[2]), "r"(a[3]), "r"(b[0]), "r"(b[1]));
}

__device__ __forceinline__ void mma_f16(float c[4], const uint32_t a[4],
                                        uint32_t b0, uint32_t b1) {
    asm volatile(
        "mma.sync.aligned.m16n8k16.row.col.f32.f16.f16.f32 "
        "{%0,%1,%2,%3},{%4,%5,%6,%7},{%8,%9},{%0,%1,%2,%3};"
        : "+f"(c[0]), "+f"(c[1]), "+f"(c[2]), "+f"(c[3])
        : "r"(a[0]), "r"(a[1]), "r"(a[2]), "r"(a[3]), "r"(b0), "r"(b1));
}

__device__ __forceinline__ uint32_t packh2(float lo, float hi) {
    __half2 h = __floats2half2_rn(lo, hi);
    return *(uint32_t*)&h;
}

// Bank-spread swizzle key for [row][pair] half2 layouts (32 words/row).
__device__ __forceinline__ int FSW(int d) { return ((d & 7) << 2) | ((d >> 3) & 3); }

// ---------------------------------------------------------------------------
// QKV projection (unchanged — known good, next round's target).
// ---------------------------------------------------------------------------
#define APAD 36
__global__ __launch_bounds__(256)
void qkv_gemm(const float* __restrict__ X,
              const float* __restrict__ Wq,
              const float* __restrict__ Wk,
              const float* __restrict__ Wv) {
    __shared__ uint32_t As[128 * APAD];
    __shared__ uint32_t Bs[128 * APAD];

    const float* W = (blockIdx.z == 0) ? Wq : (blockIdx.z == 1) ? Wk : Wv;
    float* Y       = (blockIdx.z == 0) ? g_q : (blockIdx.z == 1) ? g_k : g_v;

    const int m0 = blockIdx.y * 128;
    const int n0 = blockIdx.x * 128;
    const int tid  = threadIdx.x;
    const int warp = tid >> 5;
    const int lane = tid & 31;
    const int g = lane >> 2;
    const int t = lane & 3;
    const int wm0 = (warp >> 1) * 32;
    const int wn0 = (warp & 1) * 64;

    float acc[2][8][4];
#pragma unroll
    for (int mt = 0; mt < 2; mt++)
#pragma unroll
        for (int nt = 0; nt < 8; nt++)
#pragma unroll
            for (int e = 0; e < 4; e++) acc[mt][nt][e] = 0.0f;

    for (int k0 = 0; k0 < HID; k0 += 32) {
#pragma unroll
        for (int u = 0; u < 4; u++) {
            int idx = tid + u * 256;
            int row = idx >> 3;
            int c4  = (idx & 7) * 4;
            float4 xa = *(const float4*)&X[(size_t)(m0 + row) * HID + k0 + c4];
            As[row * APAD + c4 + 0] = f2tf32(xa.x);
            As[row * APAD + c4 + 1] = f2tf32(xa.y);
            As[row * APAD + c4 + 2] = f2tf32(xa.z);
            As[row * APAD + c4 + 3] = f2tf32(xa.w);
            float4 wb = *(const float4*)&W[(size_t)(n0 + row) * HID + k0 + c4];
            Bs[row * APAD + c4 + 0] = f2tf32(wb.x);
            Bs[row * APAD + c4 + 1] = f2tf32(wb.y);
            Bs[row * APAD + c4 + 2] = f2tf32(wb.z);
            Bs[row * APAD + c4 + 3] = f2tf32(wb.w);
        }
        __syncthreads();

#pragma unroll
        for (int kc = 0; kc < 4; kc++) {
            uint32_t a[2][4];
#pragma unroll
            for (int mt = 0; mt < 2; mt++) {
                int r = wm0 + mt * 16;
                a[mt][0] = As[(r + g)     * APAD + kc * 8 + t];
                a[mt][1] = As[(r + g + 8) * APAD + kc * 8 + t];
                a[mt][2] = As[(r + g)     * APAD + kc * 8 + t + 4];
                a[mt][3] = As[(r + g + 8) * APAD + kc * 8 + t + 4];
            }
#pragma unroll
            for (int nt = 0; nt < 8; nt++) {
                uint32_t b[2];
                int col = wn0 + nt * 8 + g;
                b[0] = Bs[col * APAD + kc * 8 + t];
                b[1] = Bs[col * APAD + kc * 8 + t + 4];
#pragma unroll
                for (int mt = 0; mt < 2; mt++) mma_tf32(acc[mt][nt], a[mt], b);
            }
        }
        __syncthreads();
    }

#pragma unroll
    for (int mt = 0; mt < 2; mt++)
#pragma unroll
        for (int nt = 0; nt < 8; nt++) {
            int row0 = m0 + wm0 + mt * 16 + g;
            int col  = n0 + wn0 + nt * 8 + 2 * t;
            *(float2*)&Y[(size_t)row0 * HID + col] =
                make_float2(acc[mt][nt][0], acc[mt][nt][1]);
            *(float2*)&Y[(size_t)(row0 + 8) * HID + col] =
                make_float2(acc[mt][nt][2], acc[mt][nt][3]);
        }
}

// ---------------------------------------------------------------------------
// RoPE tables (rope_apply is now fused into attention staging)
// ---------------------------------------------------------------------------
__global__ void rope_table() {
    int idx = blockIdx.x * blockDim.x + threadIdx.x;
    if (idx >= SEQ * 32) return;
    int s = idx >> 5;
    int j = idx & 31;
    double inv = pow(10000.0, -(double)j / 32.0);
    double a = (double)s * inv;
    g_cos[idx] = (float)cos(a);
    g_sin[idx] = (float)sin(a);
}

// ---------------------------------------------------------------------------
// Flash attention, fp16 m16n8k16. 128 threads (4 warps), 128 queries/CTA,
// 32 query rows per warp, 64-key tiles. Q frags + P live in registers.
// SMEM layouts (uint32 words, 32 half2 words per row):
//   Kh[key][pair]: word = key*32 + ((dim>>1)   ^ FSW(key))   (RoPE applied)
//   Vh[dim][pair]: word = dim*32 + ((key>>1)   ^ FSW(dim))
//   Qs[row][pair]: word = row*32 + ((dim>>1)   ^ FSW(row))   (staging only)
// ---------------------------------------------------------------------------
__global__ __launch_bounds__(128)
void attn_kernel(float* __restrict__ out) {
    __shared__ uint32_t sh[4096];     // 16 KB
    uint32_t* Kh = sh;                // 2048 words
    uint32_t* Vh = sh + 2048;         // 2048 words

    const int tid  = threadIdx.x;
    const int warp = tid >> 5;
    const int lane = tid & 31;
    const int g = lane >> 2;
    const int t = lane & 3;
    const int h = blockIdx.y & (NH - 1);
    const int b = blockIdx.y >> 4;
    const int q0 = blockIdx.x * 128;

    const float* qptr = g_q + (size_t)b * SEQ * HID + h * HD;
    const float* kptr = g_k + (size_t)b * SEQ * HID + h * HD;
    const float* vptr = g_v + (size_t)b * SEQ * HID + h * HD;

    // ---- Stage Q (RoPE + 1/8 scale) into this warp's scratch, grab frags ----
    uint32_t* Qs = sh + warp * 1024;  // 32 rows x 32 words
#pragma unroll
    for (int it = 0; it < 8; it++) {
        int idx2 = lane + it * 32;
        int dg = idx2 & 7;           // dim group: dims dg*4..+3 and +32
        int r  = idx2 >> 3;          // 0..31
        int row = q0 + warp * 32 + r;
        const float* qr = qptr + (size_t)row * HID;
        float4 lo = *(const float4*)&qr[dg * 4];
        float4 hi = *(const float4*)&qr[dg * 4 + 32];
        float4 cz = *(const float4*)&g_cos[row * 32 + dg * 4];
        float4 sz = *(const float4*)&g_sin[row * 32 + dg * 4];
        float a0 = (lo.x * cz.x - hi.x * sz.x) * 0.125f;
        float a1 = (lo.y * cz.y - hi.y * sz.y) * 0.125f;
        float a2 = (lo.z * cz.z - hi.z * sz.z) * 0.125f;
        float a3 = (lo.w * cz.w - hi.w * sz.w) * 0.125f;
        float b0 = (hi.x * cz.x + lo.x * sz.x) * 0.125f;
        float b1 = (hi.y * cz.y + lo.y * sz.y) * 0.125f;
        float b2 = (hi.z * cz.z + lo.z * sz.z) * 0.125f;
        float b3 = (hi.w * cz.w + lo.w * sz.w) * 0.125f;
        int fr = FSW(r);
        Qs[r * 32 + ((dg * 2 + 0)  ^ fr)] = packh2(a0, a1);
        Qs[r * 32 + ((dg * 2 + 1)  ^ fr)] = packh2(a2, a3);
        Qs[r * 32 + ((dg * 2 + 16) ^ fr)] = packh2(b0, b1);
        Qs[r * 32 + ((dg * 2 + 17) ^ fr)] = packh2(b2, b3);
    }
    __syncwarp();
    uint32_t qa[2][4][4];
#pragma unroll
    for (int mt = 0; mt < 2; mt++) {
        int ra = mt * 16 + g, rb = mt * 16 + 8 + g;
        int fa = FSW(ra), fb = FSW(rb);
#pragma unroll
        for (int kb = 0; kb < 4; kb++) {
            qa[mt][kb][0] = Qs[ra * 32 + ((kb * 8 + t)     ^ fa)];
            qa[mt][kb][1] = Qs[rb * 32 + ((kb * 8 + t)     ^ fb)];
            qa[mt][kb][2] = Qs[ra * 32 + ((kb * 8 + t + 4) ^ fa)];
            qa[mt][kb][3] = Qs[rb * 32 + ((kb * 8 + t + 4) ^ fb)];
        }
    }

    float m_i[2][2], l_i[2][2];
    float o[2][8][4];
#pragma unroll
    for (int mt = 0; mt < 2; mt++) {
        m_i[mt][0] = m_i[mt][1] = -1e30f;
        l_i[mt][0] = l_i[mt][1] = 0.0f;
#pragma unroll
        for (int nb = 0; nb < 8; nb++)
#pragma unroll
            for (int e = 0; e < 4; e++) o[mt][nb][e] = 0.0f;
    }

    for (int k0 = 0; k0 < SEQ; k0 += 64) {
        __syncthreads();   // Q frag reads / previous tile reads complete

        // ---- Stage K (with RoPE) ----
#pragma unroll
        for (int u = 0; u < 4; u++) {
            int idx = tid + u * 128;
            int dg = idx & 7;
            int r  = idx >> 3;        // 0..63
            int pos = k0 + r;
            const float* kr = kptr + (size_t)pos * HID;
            float4 lo = *(const float4*)&kr[dg * 4];
            float4 hi = *(const float4*)&kr[dg * 4 + 32];
            float4 cz = *(const float4*)&g_cos[pos * 32 + dg * 4];
            float4 sz = *(const float4*)&g_sin[pos * 32 + dg * 4];
            int fr = FSW(r);
            Kh[r * 32 + ((dg * 2 + 0)  ^ fr)] =
                packh2(lo.x * cz.x - hi.x * sz.x, lo.y * cz.y - hi.y * sz.y);
            Kh[r * 32 + ((dg * 2 + 1)  ^ fr)] =
                packh2(lo.z * cz.z - hi.z * sz.z, lo.w * cz.w - hi.w * sz.w);
            Kh[r * 32 + ((dg * 2 + 16) ^ fr)] =
                packh2(hi.x * cz.x + lo.x * sz.x, hi.y * cz.y + lo.y * sz.y);
            Kh[r * 32 + ((dg * 2 + 17) ^ fr)] =
                packh2(hi.z * cz.z + lo.z * sz.z, hi.w * cz.w + lo.w * sz.w);
        }
        // ---- Stage V (transposed: [dim][keypair]) ----
#pragma unroll
        for (int u = 0; u < 4; u++) {
            int idx = tid + u * 128;
            int c4 = (idx & 15) * 4;  // dim group
            int kp = idx >> 4;        // key pair 0..31
            const float* v0 = vptr + (size_t)(k0 + 2 * kp) * HID;
            float4 va = *(const float4*)&v0[c4];
            float4 vb = *(const float4*)&v0[HID + c4];
            Vh[(c4 + 0) * 32 + (kp ^ FSW(c4 + 0))] = packh2(va.x, vb.x);
            Vh[(c4 + 1) * 32 + (kp ^ FSW(c4 + 1))] = packh2(va.y, vb.y);
            Vh[(c4 + 2) * 32 + (kp ^ FSW(c4 + 2))] = packh2(va.z, vb.z);
            Vh[(c4 + 3) * 32 + (kp ^ FSW(c4 + 3))] = packh2(va.w, vb.w);
        }
        __syncthreads();

        // ---- S = Q @ K^T : 32x64 per warp ----
        float s[2][8][4];
#pragma unroll
        for (int mt = 0; mt < 2; mt++)
#pragma unroll
            for (int nb = 0; nb < 8; nb++)
#pragma unroll
                for (int e = 0; e < 4; e++) s[mt][nb][e] = 0.0f;

#pragma unroll
        for (int kb = 0; kb < 4; kb++) {
#pragma unroll
            for (int nb = 0; nb < 8; nb++) {
                int key = nb * 8 + g;
                int fk = FSW(key);
                uint32_t b0 = Kh[key * 32 + ((kb * 8 + t)     ^ fk)];
                uint32_t b1 = Kh[key * 32 + ((kb * 8 + t + 4) ^ fk)];
                mma_f16(s[0][nb], qa[0][kb], b0, b1);
                mma_f16(s[1][nb], qa[1][kb], b0, b1);
            }
        }

        // ---- Online softmax; pack P into fp16 A-frags (registers only) ----
        uint32_t pa[2][4][4];
#pragma unroll
        for (int mt = 0; mt < 2; mt++) {
#pragma unroll
            for (int hh = 0; hh < 2; hh++) {
                const int e0 = hh * 2;
                float mx = -1e30f;
#pragma unroll
                for (int nb = 0; nb < 8; nb++)
                    mx = fmaxf(mx, fmaxf(s[mt][nb][e0], s[mt][nb][e0 + 1]));
                mx = fmaxf(mx, __shfl_xor_sync(0xffffffffu, mx, 1));
                mx = fmaxf(mx, __shfl_xor_sync(0xffffffffu, mx, 2));
                float mnew = fmaxf(m_i[mt][hh], mx);
                float corr = __expf(m_i[mt][hh] - mnew);
                float rs = 0.0f;
#pragma unroll
                for (int nb = 0; nb < 8; nb++) {
                    float p0 = __expf(s[mt][nb][e0]     - mnew);
                    float p1 = __expf(s[mt][nb][e0 + 1] - mnew);
                    rs += p0 + p1;
                    s[mt][nb][e0]     = p0;
                    s[mt][nb][e0 + 1] = p1;
                }
                rs += __shfl_xor_sync(0xffffffffu, rs, 1);
                rs += __shfl_xor_sync(0xffffffffu, rs, 2);
                l_i[mt][hh] = l_i[mt][hh] * corr + rs;
                m_i[mt][hh] = mnew;
#pragma unroll
                for (int nb = 0; nb < 8; nb++) {
                    o[mt][nb][e0]     *= corr;
                    o[mt][nb][e0 + 1] *= corr;
                }
            }
            // c-layout: [0]=(g,2t) [1]=(g,2t+1) [2]=(g+8,2t) [3]=(g+8,2t+1)
            // A-frag kb: a0=(g,16kb+2t,+1) a1=(g+8,..) a2=(g,16kb+8+2t,+1) a3=(g+8,..)
#pragma unroll
            for (int kb = 0; kb < 4; kb++) {
                pa[mt][kb][0] = packh2(s[mt][2 * kb][0],     s[mt][2 * kb][1]);
                pa[mt][kb][1] = packh2(s[mt][2 * kb][2],     s[mt][2 * kb][3]);
                pa[mt][kb][2] = packh2(s[mt][2 * kb + 1][0], s[mt][2 * kb + 1][1]);
                pa[mt][kb][3] = packh2(s[mt][2 * kb + 1][2], s[mt][2 * kb + 1][3]);
            }
        }

        // ---- ctx += P @ V : 32x64 per warp ----
#pragma unroll
        for (int kb = 0; kb < 4; kb++) {
#pragma unroll
            for (int nb = 0; nb < 8; nb++) {
                int dim = nb * 8 + g;
                int fd = FSW(dim);
                uint32_t b0 = Vh[dim * 32 + ((kb * 8 + t)     ^ fd)];
                uint32_t b1 = Vh[dim * 32 + ((kb * 8 + t + 4) ^ fd)];
                mma_f16(o[0][nb], pa[0][kb], b0, b1);
                mma_f16(o[1][nb], pa[1][kb], b0, b1);
            }
        }
    }

    // ---- Normalize and write out[b, s, h*64 + d] ----
#pragma unroll
    for (int mt = 0; mt < 2; mt++)
#pragma unroll
        for (int hh = 0; hh < 2; hh++) {
            float inv_l = 1.0f / l_i[mt][hh];
            int row = q0 + warp * 32 + mt * 16 + g + 8 * hh;
#pragma unroll
            for (int nb = 0; nb < 8; nb++) {
                size_t base = (size_t)(b * SEQ + row) * HID + h * HD + nb * 8 + 2 * t;
                *(float2*)&out[base] = make_float2(o[mt][nb][2 * hh]     * inv_l,
                                                   o[mt][nb][2 * hh + 1] * inv_l);
            }
        }
}

// ---------------------------------------------------------------------------
extern "C" void kernel_launch(void* const* d_in, const int* in_sizes, int n_in,
                              void* d_out, int out_size) {
    const float* X  = (const float*)d_in[0];
    const float* Wq = (const float*)d_in[1];
    const float* Wk = (const float*)d_in[2];
    const float* Wv = (const float*)d_in[3];
    float* out = (float*)d_out;

    qkv_gemm<<<dim3(HID / 128, MROWS / 128, 3), 256>>>(X, Wq, Wk, Wv);
    rope_table<<<(SEQ * 32 + 255) / 256, 256>>>();
    attn_kernel<<<dim3(SEQ / 128, NH * BATCH), 128>>>(out);
}

// round 8
// speedup vs baseline: 5.0333x; 1.1484x over previous
#include <cuda_runtime.h>
#include <cuda_fp16.h>
#include <math.h>
#include <stdint.h>

#define BATCH 2
#define SEQ   2048
#define NH    16
#define HD    64
#define HID   1024            // NH*HD
#define MROWS (BATCH*SEQ)     // 4096

// Scratch (no allocations allowed)
__device__ float g_q[MROWS * HID];
__device__ float g_k[MROWS * HID];
__device__ float g_v[MROWS * HID];
__device__ float g_cos[SEQ * 32];
__device__ float g_sin[SEQ * 32];

__device__ __forceinline__ void mma_f16(float c[4], const uint32_t a[4],
                                        uint32_t b0, uint32_t b1) {
    asm volatile(
        "mma.sync.aligned.m16n8k16.row.col.f32.f16.f16.f32 "
        "{%0,%1,%2,%3},{%4,%5,%6,%7},{%8,%9},{%0,%1,%2,%3};"
        : "+f"(c[0]), "+f"(c[1]), "+f"(c[2]), "+f"(c[3])
        : "r"(a[0]), "r"(a[1]), "r"(a[2]), "r"(a[3]), "r"(b0), "r"(b1));
}

__device__ __forceinline__ uint32_t packh2(float lo, float hi) {
    __half2 h = __floats2half2_rn(lo, hi);
    return *(uint32_t*)&h;
}

// Bank-spread swizzle key for [row][pair] half2 layouts (32 words/row).
__device__ __forceinline__ int FSW(int d) { return ((d & 7) << 2) | ((d >> 3) & 3); }

// ---------------------------------------------------------------------------
// QKV projection, fp16 m16n8k16: Y = X @ W^T.
// X[M,K] row-major, W[N,K] row-major. blockIdx.z selects q/k/v.
// Block tile 128x128, K-step 32. 8 warps in 4x2 (warp tile 32x64).
// SMEM: half2 words, 16 pairs/row padded to 20 (bank stride 20 => rows 0..7
// of any g-lane group land in distinct banks; no XOR math needed).
// ---------------------------------------------------------------------------
#define QPAD 20
__global__ __launch_bounds__(256)
void qkv_gemm(const float* __restrict__ X,
              const float* __restrict__ Wq,
              const float* __restrict__ Wk,
              const float* __restrict__ Wv) {
    __shared__ uint32_t As2[128 * QPAD];
    __shared__ uint32_t Bs2[128 * QPAD];

    const float* W = (blockIdx.z == 0) ? Wq : (blockIdx.z == 1) ? Wk : Wv;
    float* Y       = (blockIdx.z == 0) ? g_q : (blockIdx.z == 1) ? g_k : g_v;

    const int m0 = blockIdx.y * 128;
    const int n0 = blockIdx.x * 128;
    const int tid  = threadIdx.x;
    const int warp = tid >> 5;
    const int lane = tid & 31;
    const int g = lane >> 2;
    const int t = lane & 3;
    const int wm0 = (warp >> 1) * 32;   // 0,32,64,96
    const int wn0 = (warp & 1) * 64;    // 0,64

    float acc[2][8][4];
#pragma unroll
    for (int mt = 0; mt < 2; mt++)
#pragma unroll
        for (int nt = 0; nt < 8; nt++)
#pragma unroll
            for (int e = 0; e < 4; e++) acc[mt][nt][e] = 0.0f;

    for (int k0 = 0; k0 < HID; k0 += 32) {
        // Stage A and B tiles: 128 rows x 32 cols fp32 -> half2 pairs
#pragma unroll
        for (int u = 0; u < 4; u++) {
            int idx = tid + u * 256;
            int row = idx >> 3;          // 0..127
            int c4  = (idx & 7) * 4;     // 0..28
            int w0  = row * QPAD + (c4 >> 1);
            float4 xa = *(const float4*)&X[(size_t)(m0 + row) * HID + k0 + c4];
            As2[w0]     = packh2(xa.x, xa.y);
            As2[w0 + 1] = packh2(xa.z, xa.w);
            float4 wb = *(const float4*)&W[(size_t)(n0 + row) * HID + k0 + c4];
            Bs2[w0]     = packh2(wb.x, wb.y);
            Bs2[w0 + 1] = packh2(wb.z, wb.w);
        }
        __syncthreads();

#pragma unroll
        for (int kb = 0; kb < 2; kb++) {
            uint32_t a[2][4];
#pragma unroll
            for (int mt = 0; mt < 2; mt++) {
                int ra = (wm0 + mt * 16 + g) * QPAD;
                int rb = (wm0 + mt * 16 + 8 + g) * QPAD;
                a[mt][0] = As2[ra + kb * 8 + t];
                a[mt][1] = As2[rb + kb * 8 + t];
                a[mt][2] = As2[ra + kb * 8 + 4 + t];
                a[mt][3] = As2[rb + kb * 8 + 4 + t];
            }
#pragma unroll
            for (int nt = 0; nt < 8; nt++) {
                int rc = (wn0 + nt * 8 + g) * QPAD;
                uint32_t b0 = Bs2[rc + kb * 8 + t];
                uint32_t b1 = Bs2[rc + kb * 8 + 4 + t];
                mma_f16(acc[0][nt], a[0], b0, b1);
                mma_f16(acc[1][nt], a[1], b0, b1);
            }
        }
        __syncthreads();
    }

#pragma unroll
    for (int mt = 0; mt < 2; mt++)
#pragma unroll
        for (int nt = 0; nt < 8; nt++) {
            int row0 = m0 + wm0 + mt * 16 + g;
            int col  = n0 + wn0 + nt * 8 + 2 * t;
            *(float2*)&Y[(size_t)row0 * HID + col] =
                make_float2(acc[mt][nt][0], acc[mt][nt][1]);
            *(float2*)&Y[(size_t)(row0 + 8) * HID + col] =
                make_float2(acc[mt][nt][2], acc[mt][nt][3]);
        }
}

// ---------------------------------------------------------------------------
// RoPE tables (apply is fused into attention staging)
// ---------------------------------------------------------------------------
__global__ void rope_table() {
    int idx = blockIdx.x * blockDim.x + threadIdx.x;
    if (idx >= SEQ * 32) return;
    int s = idx >> 5;
    int j = idx & 31;
    double inv = pow(10000.0, -(double)j / 32.0);
    double a = (double)s * inv;
    g_cos[idx] = (float)cos(a);
    g_sin[idx] = (float)sin(a);
}

// ---------------------------------------------------------------------------
// Flash attention, fp16 m16n8k16 (unchanged from round 6 — known good).
// ---------------------------------------------------------------------------
__global__ __launch_bounds__(128)
void attn_kernel(float* __restrict__ out) {
    __shared__ uint32_t sh[4096];     // 16 KB
    uint32_t* Kh = sh;                // 2048 words
    uint32_t* Vh = sh + 2048;         // 2048 words

    const int tid  = threadIdx.x;
    const int warp = tid >> 5;
    const int lane = tid & 31;
    const int g = lane >> 2;
    const int t = lane & 3;
    const int h = blockIdx.y & (NH - 1);
    const int b = blockIdx.y >> 4;
    const int q0 = blockIdx.x * 128;

    const float* qptr = g_q + (size_t)b * SEQ * HID + h * HD;
    const float* kptr = g_k + (size_t)b * SEQ * HID + h * HD;
    const float* vptr = g_v + (size_t)b * SEQ * HID + h * HD;

    // ---- Stage Q (RoPE + 1/8 scale) into this warp's scratch, grab frags ----
    uint32_t* Qs = sh + warp * 1024;  // 32 rows x 32 words
#pragma unroll
    for (int it = 0; it < 8; it++) {
        int idx2 = lane + it * 32;
        int dg = idx2 & 7;
        int r  = idx2 >> 3;
        int row = q0 + warp * 32 + r;
        const float* qr = qptr + (size_t)row * HID;
        float4 lo = *(const float4*)&qr[dg * 4];
        float4 hi = *(const float4*)&qr[dg * 4 + 32];
        float4 cz = *(const float4*)&g_cos[row * 32 + dg * 4];
        float4 sz = *(const float4*)&g_sin[row * 32 + dg * 4];
        float a0 = (lo.x * cz.x - hi.x * sz.x) * 0.125f;
        float a1 = (lo.y * cz.y - hi.y * sz.y) * 0.125f;
        float a2 = (lo.z * cz.z - hi.z * sz.z) * 0.125f;
        float a3 = (lo.w * cz.w - hi.w * sz.w) * 0.125f;
        float b0 = (hi.x * cz.x + lo.x * sz.x) * 0.125f;
        float b1 = (hi.y * cz.y + lo.y * sz.y) * 0.125f;
        float b2 = (hi.z * cz.z + lo.z * sz.z) * 0.125f;
        float b3 = (hi.w * cz.w + lo.w * sz.w) * 0.125f;
        int fr = FSW(r);
        Qs[r * 32 + ((dg * 2 + 0)  ^ fr)] = packh2(a0, a1);
        Qs[r * 32 + ((dg * 2 + 1)  ^ fr)] = packh2(a2, a3);
        Qs[r * 32 + ((dg * 2 + 16) ^ fr)] = packh2(b0, b1);
        Qs[r * 32 + ((dg * 2 + 17) ^ fr)] = packh2(b2, b3);
    }
    __syncwarp();
    uint32_t qa[2][4][4];
#pragma unroll
    for (int mt = 0; mt < 2; mt++) {
        int ra = mt * 16 + g, rb = mt * 16 + 8 + g;
        int fa = FSW(ra), fb = FSW(rb);
#pragma unroll
        for (int kb = 0; kb < 4; kb++) {
            qa[mt][kb][0] = Qs[ra * 32 + ((kb * 8 + t)     ^ fa)];
            qa[mt][kb][1] = Qs[rb * 32 + ((kb * 8 + t)     ^ fb)];
            qa[mt][kb][2] = Qs[ra * 32 + ((kb * 8 + t + 4) ^ fa)];
            qa[mt][kb][3] = Qs[rb * 32 + ((kb * 8 + t + 4) ^ fb)];
        }
    }

    float m_i[2][2], l_i[2][2];
    float o[2][8][4];
#pragma unroll
    for (int mt = 0; mt < 2; mt++) {
        m_i[mt][0] = m_i[mt][1] = -1e30f;
        l_i[mt][0] = l_i[mt][1] = 0.0f;
#pragma unroll
        for (int nb = 0; nb < 8; nb++)
#pragma unroll
            for (int e = 0; e < 4; e++) o[mt][nb][e] = 0.0f;
    }

    for (int k0 = 0; k0 < SEQ; k0 += 64) {
        __syncthreads();

        // ---- Stage K (with RoPE) ----
#pragma unroll
        for (int u = 0; u < 4; u++) {
            int idx = tid + u * 128;
            int dg = idx & 7;
            int r  = idx >> 3;
            int pos = k0 + r;
            const float* kr = kptr + (size_t)pos * HID;
            float4 lo = *(const float4*)&kr[dg * 4];
            float4 hi = *(const float4*)&kr[dg * 4 + 32];
            float4 cz = *(const float4*)&g_cos[pos * 32 + dg * 4];
            float4 sz = *(const float4*)&g_sin[pos * 32 + dg * 4];
            int fr = FSW(r);
            Kh[r * 32 + ((dg * 2 + 0)  ^ fr)] =
                packh2(lo.x * cz.x - hi.x * sz.x, lo.y * cz.y - hi.y * sz.y);
            Kh[r * 32 + ((dg * 2 + 1)  ^ fr)] =
                packh2(lo.z * cz.z - hi.z * sz.z, lo.w * cz.w - hi.w * sz.w);
            Kh[r * 32 + ((dg * 2 + 16) ^ fr)] =
                packh2(hi.x * cz.x + lo.x * sz.x, hi.y * cz.y + lo.y * sz.y);
            Kh[r * 32 + ((dg * 2 + 17) ^ fr)] =
                packh2(hi.z * cz.z + lo.z * sz.z, hi.w * cz.w + lo.w * sz.w);
        }
        // ---- Stage V (transposed: [dim][keypair]) ----
#pragma unroll
        for (int u = 0; u < 4; u++) {
            int idx = tid + u * 128;
            int c4 = (idx & 15) * 4;
            int kp = idx >> 4;
            const float* v0 = vptr + (size_t)(k0 + 2 * kp) * HID;
            float4 va = *(const float4*)&v0[c4];
            float4 vb = *(const float4*)&v0[HID + c4];
            Vh[(c4 + 0) * 32 + (kp ^ FSW(c4 + 0))] = packh2(va.x, vb.x);
            Vh[(c4 + 1) * 32 + (kp ^ FSW(c4 + 1))] = packh2(va.y, vb.y);
            Vh[(c4 + 2) * 32 + (kp ^ FSW(c4 + 2))] = packh2(va.z, vb.z);
            Vh[(c4 + 3) * 32 + (kp ^ FSW(c4 + 3))] = packh2(va.w, vb.w);
        }
        __syncthreads();

        // ---- S = Q @ K^T : 32x64 per warp ----
        float s[2][8][4];
#pragma unroll
        for (int mt = 0; mt < 2; mt++)
#pragma unroll
            for (int nb = 0; nb < 8; nb++)
#pragma unroll
                for (int e = 0; e < 4; e++) s[mt][nb][e] = 0.0f;

#pragma unroll
        for (int kb = 0; kb < 4; kb++) {
#pragma unroll
            for (int nb = 0; nb < 8; nb++) {
                int key = nb * 8 + g;
                int fk = FSW(key);
                uint32_t b0 = Kh[key * 32 + ((kb * 8 + t)     ^ fk)];
                uint32_t b1 = Kh[key * 32 + ((kb * 8 + t + 4) ^ fk)];
                mma_f16(s[0][nb], qa[0][kb], b0, b1);
                mma_f16(s[1][nb], qa[1][kb], b0, b1);
            }
        }

        // ---- Online softmax; pack P into fp16 A-frags (registers only) ----
        uint32_t pa[2][4][4];
#pragma unroll
        for (int mt = 0; mt < 2; mt++) {
#pragma unroll
            for (int hh = 0; hh < 2; hh++) {
                const int e0 = hh * 2;
                float mx = -1e30f;
#pragma unroll
                for (int nb = 0; nb < 8; nb++)
                    mx = fmaxf(mx, fmaxf(s[mt][nb][e0], s[mt][nb][e0 + 1]));
                mx = fmaxf(mx, __shfl_xor_sync(0xffffffffu, mx, 1));
                mx = fmaxf(mx, __shfl_xor_sync(0xffffffffu, mx, 2));
                float mnew = fmaxf(m_i[mt][hh], mx);
                float corr = __expf(m_i[mt][hh] - mnew);
                float rs = 0.0f;
#pragma unroll
                for (int nb = 0; nb < 8; nb++) {
                    float p0 = __expf(s[mt][nb][e0]     - mnew);
                    float p1 = __expf(s[mt][nb][e0 + 1] - mnew);
                    rs += p0 + p1;
                    s[mt][nb][e0]     = p0;
                    s[mt][nb][e0 + 1] = p1;
                }
                rs += __shfl_xor_sync(0xffffffffu, rs, 1);
                rs += __shfl_xor_sync(0xffffffffu, rs, 2);
                l_i[mt][hh] = l_i[mt][hh] * corr + rs;
                m_i[mt][hh] = mnew;
#pragma unroll
                for (int nb = 0; nb < 8; nb++) {
                    o[mt][nb][e0]     *= corr;
                    o[mt][nb][e0 + 1] *= corr;
                }
            }
#pragma unroll
            for (int kb = 0; kb < 4; kb++) {
                pa[mt][kb][0] = packh2(s[mt][2 * kb][0],     s[mt][2 * kb][1]);
                pa[mt][kb][1] = packh2(s[mt][2 * kb][2],     s[mt][2 * kb][3]);
                pa[mt][kb][2] = packh2(s[mt][2 * kb + 1][0], s[mt][2 * kb + 1][1]);
                pa[mt][kb][3] = packh2(s[mt][2 * kb + 1][2], s[mt][2 * kb + 1][3]);
            }
        }

        // ---- ctx += P @ V : 32x64 per warp ----
#pragma unroll
        for (int kb = 0; kb < 4; kb++) {
#pragma unroll
            for (int nb = 0; nb < 8; nb++) {
                int dim = nb * 8 + g;
                int fd = FSW(dim);
                uint32_t b0 = Vh[dim * 32 + ((kb * 8 + t)     ^ fd)];
                uint32_t b1 = Vh[dim * 32 + ((kb * 8 + t + 4) ^ fd)];
                mma_f16(o[0][nb], pa[0][kb], b0, b1);
                mma_f16(o[1][nb], pa[1][kb], b0, b1);
            }
        }
    }

    // ---- Normalize and write out[b, s, h*64 + d] ----
#pragma unroll
    for (int mt = 0; mt < 2; mt++)
#pragma unroll
        for (int hh = 0; hh < 2; hh++) {
            float inv_l = 1.0f / l_i[mt][hh];
            int row = q0 + warp * 32 + mt * 16 + g + 8 * hh;
#pragma unroll
            for (int nb = 0; nb < 8; nb++) {
                size_t base = (size_t)(b * SEQ + row) * HID + h * HD + nb * 8 + 2 * t;
                *(float2*)&out[base] = make_float2(o[mt][nb][2 * hh]     * inv_l,
                                                   o[mt][nb][2 * hh + 1] * inv_l);
            }
        }
}

// ---------------------------------------------------------------------------
extern "C" void kernel_launch(void* const* d_in, const int* in_sizes, int n_in,
                              void* d_out, int out_size) {
    const float* X  = (const float*)d_in[0];
    const float* Wq = (const float*)d_in[1];
    const float* Wk = (const float*)d_in[2];
    const float* Wv = (const float*)d_in[3];
    float* out = (float*)d_out;

    qkv_gemm<<<dim3(HID / 128, MROWS / 128, 3), 256>>>(X, Wq, Wk, Wv);
    rope_table<<<(SEQ * 32 + 255) / 256, 256>>>();
    attn_kernel<<<dim3(SEQ / 128, NH * BATCH), 128>>>(out);
}